// round 1
// baseline (speedup 1.0000x reference)
#include <cuda_runtime.h>
#include <math.h>

#define Bb 2
#define Ss 2048
#define Ee 512
#define Hh 8
#define DHh 64
#define Ww 5
#define PADp 2
#define SKk 2044
#define HIDh 2048
#define Ll 6
#define OUTo 6
#define Ff 320            // DH * W
#define SCALEc 0.125f     // DH^-0.5
#define CHUNKS 128

// ---------------- scratch (static device globals; no allocation) ----------------
__device__ float g_x[Bb * Ss * Ee];                       // 8 MB  current activations
__device__ float g_q[Bb * Ss * Ee];                       // 8 MB
__device__ float g_k[Bb * Ss * Ee];                       // 8 MB
__device__ float g_v[Bb * Ss * Ee];                       // 8 MB
__device__ float g_qu[(size_t)Bb * Hh * Ss * Ff];         // 33.5 MB
__device__ float g_ku[(size_t)Bb * Hh * SKk * Ff];        // 33.4 MB
__device__ float g_vs[(size_t)Bb * Hh * SKk * DHh];       // 8.4 MB
__device__ float g_sc[(size_t)Bb * Hh * Ss * SKk];        // 268 MB scores
__device__ float g_attn[Bb * Ss * Ee];                    // 8 MB
__device__ float g_hid[(size_t)Bb * Ss * HIDh];           // 33.5 MB
__device__ float g_part[Bb * CHUNKS * OUTo];

// ---------------- embedding + positional encoding ----------------
__global__ void k_embed(const int* __restrict__ inp, const float* __restrict__ emb) {
    int idx = blockIdx.x * blockDim.x + threadIdx.x;    // over B*S*E
    if (idx >= Bb * Ss * Ee) return;
    int e = idx % Ee;
    int bs = idx / Ee;              // b*S + s
    int s = bs % Ss;
    int tok = inp[bs];
    const float LN1E4 = 9.210340371976184f;             // ln(10000)
    int ebase = e & ~1;
    float freq = expf(-(float)ebase * (LN1E4 / (float)Ee));
    float ang = (float)s * freq;
    float pe = (e & 1) ? cosf(ang) : sinf(ang);
    g_x[idx] = emb[(size_t)tok * Ee + e] + pe;
}

// ---------------- generic tiled GEMM: C = A[MxK] @ W[KxN] + bias (+res)(+relu) ----
// M % 64 == 0, N % 64 == 0, K % 16 == 0 (true for all uses of this kernel)
template <int RELU, int RES>
__launch_bounds__(256)
__global__ void k_gemm(const float* __restrict__ A, const float* __restrict__ Wm,
                       const float* __restrict__ bias, const float* __restrict__ res,
                       float* __restrict__ C, int M, int N, int K) {
    __shared__ float As[64][17];
    __shared__ float Bs[16][65];
    int t = threadIdx.x;
    int tx = t & 15, ty = t >> 4;
    int bm = blockIdx.y * 64, bn = blockIdx.x * 64;
    float acc[4][4] = {};
    for (int k0 = 0; k0 < K; k0 += 16) {
        #pragma unroll
        for (int i = t; i < 1024; i += 256) {
            int r = i >> 4, c = i & 15;
            As[r][c] = A[(size_t)(bm + r) * K + (k0 + c)];
        }
        #pragma unroll
        for (int i = t; i < 1024; i += 256) {
            int r = i >> 6, c = i & 63;
            Bs[r][c] = Wm[(size_t)(k0 + r) * N + (bn + c)];
        }
        __syncthreads();
        #pragma unroll
        for (int kk = 0; kk < 16; kk++) {
            float a[4], bb[4];
            #pragma unroll
            for (int i = 0; i < 4; i++) a[i] = As[ty * 4 + i][kk];
            #pragma unroll
            for (int j = 0; j < 4; j++) bb[j] = Bs[kk][tx * 4 + j];
            #pragma unroll
            for (int i = 0; i < 4; i++)
                #pragma unroll
                for (int j = 0; j < 4; j++) acc[i][j] = fmaf(a[i], bb[j], acc[i][j]);
        }
        __syncthreads();
    }
    #pragma unroll
    for (int i = 0; i < 4; i++) {
        int r = bm + ty * 4 + i;
        #pragma unroll
        for (int j = 0; j < 4; j++) {
            int c = bn + tx * 4 + j;
            float v = acc[i][j] + bias[c];
            if (RES) v += res[(size_t)r * N + c];
            if (RELU) v = fmaxf(v, 0.0f);
            C[(size_t)r * N + c] = v;
        }
    }
}

// ---------------- build unfolded Q (zero padded), f = d*W + j ----------------
__global__ void k_build_qu() {
    size_t idx = (size_t)blockIdx.x * blockDim.x + threadIdx.x;
    if (idx >= (size_t)Bb * Hh * Ss * Ff) return;
    int f = (int)(idx % Ff);
    size_t r = idx / Ff;
    int q = (int)(r % Ss);
    size_t bh = r / Ss;
    int h = (int)(bh % Hh);
    int b = (int)(bh / Hh);
    int d = f / Ww, j = f % Ww;
    int src = q + j - PADp;
    float v = 0.0f;
    if (src >= 0 && src < Ss)
        v = g_q[((size_t)b * Ss + src) * Ee + h * DHh + d];
    g_qu[idx] = v;
}

__global__ void k_build_ku() {
    size_t idx = (size_t)blockIdx.x * blockDim.x + threadIdx.x;
    if (idx >= (size_t)Bb * Hh * SKk * Ff) return;
    int f = (int)(idx % Ff);
    size_t r = idx / Ff;
    int k = (int)(r % SKk);
    size_t bh = r / SKk;
    int h = (int)(bh % Hh);
    int b = (int)(bh / Hh);
    int d = f / Ww, j = f % Ww;
    g_ku[idx] = g_k[((size_t)b * Ss + (k + j)) * Ee + h * DHh + d];
}

__global__ void k_build_vs() {
    size_t idx = (size_t)blockIdx.x * blockDim.x + threadIdx.x;
    if (idx >= (size_t)Bb * Hh * SKk * DHh) return;
    int d = (int)(idx % DHh);
    size_t r = idx / DHh;
    int k = (int)(r % SKk);
    size_t bh = r / SKk;
    int h = (int)(bh % Hh);
    int b = (int)(bh / Hh);
    float s = 0.0f;
    #pragma unroll
    for (int j = 0; j < Ww; j++)
        s += g_v[((size_t)b * Ss + (k + j)) * Ee + h * DHh + d];
    g_vs[idx] = s;
}

// ---------------- scores = SCALE * Qu @ Ku^T  (batched over b*h) -------------
__launch_bounds__(256)
__global__ void k_scores() {
    int bh = blockIdx.z;
    const float* A = g_qu + (size_t)bh * Ss * Ff;   // [S, F]
    const float* Bm = g_ku + (size_t)bh * SKk * Ff; // [SK, F]
    float* C = g_sc + (size_t)bh * Ss * SKk;        // [S, SK]
    __shared__ float As[64][17];
    __shared__ float Bs[16][65];
    int t = threadIdx.x;
    int tx = t & 15, ty = t >> 4;
    int bm = blockIdx.y * 64, bn = blockIdx.x * 64;
    float acc[4][4] = {};
    for (int k0 = 0; k0 < Ff; k0 += 16) {
        #pragma unroll
        for (int i = t; i < 1024; i += 256) {
            int r = i >> 4, c = i & 15;
            As[r][c] = A[(size_t)(bm + r) * Ff + (k0 + c)];
        }
        #pragma unroll
        for (int i = t; i < 1024; i += 256) {
            int r = i >> 4, c = i & 15;
            int n = bn + r;
            Bs[c][r] = (n < SKk) ? Bm[(size_t)n * Ff + (k0 + c)] : 0.0f;
        }
        __syncthreads();
        #pragma unroll
        for (int kk = 0; kk < 16; kk++) {
            float a[4], bb[4];
            #pragma unroll
            for (int i = 0; i < 4; i++) a[i] = As[ty * 4 + i][kk];
            #pragma unroll
            for (int j = 0; j < 4; j++) bb[j] = Bs[kk][tx * 4 + j];
            #pragma unroll
            for (int i = 0; i < 4; i++)
                #pragma unroll
                for (int j = 0; j < 4; j++) acc[i][j] = fmaf(a[i], bb[j], acc[i][j]);
        }
        __syncthreads();
    }
    #pragma unroll
    for (int i = 0; i < 4; i++) {
        int r = bm + ty * 4 + i;
        #pragma unroll
        for (int j = 0; j < 4; j++) {
            int c = bn + tx * 4 + j;
            if (c < SKk) C[(size_t)r * SKk + c] = acc[i][j] * SCALEc;
        }
    }
}

// ---------------- row softmax over SK, in place ----------------
__launch_bounds__(256)
__global__ void k_softmax() {
    size_t row = blockIdx.x;                 // B*H*S rows
    float* p = g_sc + row * SKk;
    __shared__ float red[256];
    int t = threadIdx.x;
    float m = -1e30f;
    for (int i = t; i < SKk; i += 256) m = fmaxf(m, p[i]);
    red[t] = m; __syncthreads();
    for (int off = 128; off > 0; off >>= 1) {
        if (t < off) red[t] = fmaxf(red[t], red[t + off]);
        __syncthreads();
    }
    m = red[0]; __syncthreads();
    float s = 0.0f;
    for (int i = t; i < SKk; i += 256) {
        float e = expf(p[i] - m);
        p[i] = e;
        s += e;
    }
    red[t] = s; __syncthreads();
    for (int off = 128; off > 0; off >>= 1) {
        if (t < off) red[t] += red[t + off];
        __syncthreads();
    }
    float inv = 1.0f / red[0];
    for (int i = t; i < SKk; i += 256) p[i] *= inv;
}

// ---------------- O = A @ Vsum, scattered back into [B,S,E] ----------------
__launch_bounds__(256)
__global__ void k_av() {
    int bh = blockIdx.z;
    int b = bh >> 3, h = bh & 7;
    const float* A = g_sc + (size_t)bh * Ss * SKk;   // [S, SK]
    const float* Bv = g_vs + (size_t)bh * SKk * DHh; // [SK, 64]
    float* C = g_attn + (size_t)b * Ss * Ee + h * DHh; // ldc = E
    __shared__ float As[64][17];
    __shared__ float Bs[16][65];
    int t = threadIdx.x;
    int tx = t & 15, ty = t >> 4;
    int bm = blockIdx.y * 64;
    float acc[4][4] = {};
    for (int k0 = 0; k0 < SKk; k0 += 16) {
        #pragma unroll
        for (int i = t; i < 1024; i += 256) {
            int r = i >> 4, c = i & 15;
            int kk = k0 + c;
            As[r][c] = (kk < SKk) ? A[(size_t)(bm + r) * SKk + kk] : 0.0f;
        }
        #pragma unroll
        for (int i = t; i < 1024; i += 256) {
            int r = i >> 6, c = i & 63;
            int kk = k0 + r;
            Bs[r][c] = (kk < SKk) ? Bv[(size_t)kk * DHh + c] : 0.0f;
        }
        __syncthreads();
        #pragma unroll
        for (int kk = 0; kk < 16; kk++) {
            float a[4], bb[4];
            #pragma unroll
            for (int i = 0; i < 4; i++) a[i] = As[ty * 4 + i][kk];
            #pragma unroll
            for (int j = 0; j < 4; j++) bb[j] = Bs[kk][tx * 4 + j];
            #pragma unroll
            for (int i = 0; i < 4; i++)
                #pragma unroll
                for (int j = 0; j < 4; j++) acc[i][j] = fmaf(a[i], bb[j], acc[i][j]);
        }
        __syncthreads();
    }
    #pragma unroll
    for (int i = 0; i < 4; i++) {
        int r = bm + ty * 4 + i;
        #pragma unroll
        for (int j = 0; j < 4; j++) {
            int c = tx * 4 + j;
            C[(size_t)r * Ee + c] = acc[i][j];
        }
    }
}

// ---------------- LayerNorm over last dim E ----------------
__launch_bounds__(256)
__global__ void k_ln(const float* __restrict__ in, const float* __restrict__ w,
                     const float* __restrict__ bz, float* __restrict__ out) {
    int row = blockIdx.x;                       // B*S rows
    const float* x = in + (size_t)row * Ee;
    __shared__ float red[256];
    int t = threadIdx.x;
    float s = 0.0f;
    for (int i = t; i < Ee; i += 256) s += x[i];
    red[t] = s; __syncthreads();
    for (int off = 128; off > 0; off >>= 1) {
        if (t < off) red[t] += red[t + off];
        __syncthreads();
    }
    float m = red[0] * (1.0f / Ee);
    __syncthreads();
    float vs = 0.0f;
    for (int i = t; i < Ee; i += 256) { float d = x[i] - m; vs += d * d; }
    red[t] = vs; __syncthreads();
    for (int off = 128; off > 0; off >>= 1) {
        if (t < off) red[t] += red[t + off];
        __syncthreads();
    }
    float var = red[0] * (1.0f / Ee);
    float inv = 1.0f / sqrtf(var + 1e-5f);
    for (int i = t; i < Ee; i += 256)
        out[(size_t)row * Ee + i] = (x[i] - m) * inv * w[i] + bz[i];
}

// ---------------- final projection: out[b,o] = sum_i x[b,i]*W[i,o] + b[o] -----
__launch_bounds__(256)
__global__ void k_out_partial(const float* __restrict__ ow) {
    int b = blockIdx.y, c = blockIdx.x;
    const int per = (Ss * Ee) / CHUNKS;   // 8192
    const float* x = g_x + (size_t)b * Ss * Ee + (size_t)c * per;
    const float* wr = ow + (size_t)c * per * OUTo;
    int t = threadIdx.x;
    float acc[OUTo] = {};
    for (int i = t; i < per; i += 256) {
        float xv = x[i];
        #pragma unroll
        for (int o = 0; o < OUTo; o++) acc[o] = fmaf(xv, wr[(size_t)i * OUTo + o], acc[o]);
    }
    __shared__ float red[256 * OUTo];
    #pragma unroll
    for (int o = 0; o < OUTo; o++) red[t * OUTo + o] = acc[o];
    __syncthreads();
    for (int off = 128; off > 0; off >>= 1) {
        if (t < off) {
            #pragma unroll
            for (int o = 0; o < OUTo; o++)
                red[t * OUTo + o] += red[(t + off) * OUTo + o];
        }
        __syncthreads();
    }
    if (t == 0) {
        #pragma unroll
        for (int o = 0; o < OUTo; o++)
            g_part[((size_t)b * CHUNKS + c) * OUTo + o] = red[o];
    }
}

__global__ void k_out_final(const float* __restrict__ ob, float* __restrict__ out) {
    int b = blockIdx.x;
    int o = threadIdx.x;
    if (o < OUTo) {
        float s = ob[o];
        for (int c = 0; c < CHUNKS; c++) s += g_part[(b * CHUNKS + c) * OUTo + o];
        out[b * OUTo + o] = s;
    }
}

// ---------------- host launcher ----------------
extern "C" void kernel_launch(void* const* d_in, const int* in_sizes, int n_in,
                              void* d_out, int out_size) {
    const int*   inputs = (const int*)d_in[0];
    const float* emb    = (const float*)d_in[1];
    const float* ln_w   = (const float*)d_in[2];
    const float* ln_b   = (const float*)d_in[3];
    const float* q_w    = (const float*)d_in[4];
    const float* q_b    = (const float*)d_in[5];
    const float* k_w    = (const float*)d_in[6];
    const float* k_b    = (const float*)d_in[7];
    const float* v_w    = (const float*)d_in[8];
    const float* v_b    = (const float*)d_in[9];
    const float* fc1_w  = (const float*)d_in[10];
    const float* fc1_b  = (const float*)d_in[11];
    const float* fc2_w  = (const float*)d_in[12];
    const float* fc2_b  = (const float*)d_in[13];
    const float* out_w  = (const float*)d_in[14];
    const float* out_b  = (const float*)d_in[15];
    float* out = (float*)d_out;

    float *px, *pq, *pk, *pv, *pattn, *phid;
    cudaGetSymbolAddress((void**)&px,    g_x);
    cudaGetSymbolAddress((void**)&pq,    g_q);
    cudaGetSymbolAddress((void**)&pk,    g_k);
    cudaGetSymbolAddress((void**)&pv,    g_v);
    cudaGetSymbolAddress((void**)&pattn, g_attn);
    cudaGetSymbolAddress((void**)&phid,  g_hid);

    const int M = Bb * Ss;  // 4096

    // embed + positional encoding -> g_x
    k_embed<<<(Bb * Ss * Ee + 255) / 256, 256>>>(inputs, emb);

    for (int l = 0; l < Ll; l++) {
        // QKV projections
        dim3 gq(Ee / 64, M / 64);
        k_gemm<0, 0><<<gq, 256>>>(px, q_w, q_b, nullptr, pq, M, Ee, Ee);
        k_gemm<0, 0><<<gq, 256>>>(px, k_w, k_b, nullptr, pk, M, Ee, Ee);
        k_gemm<0, 0><<<gq, 256>>>(px, v_w, v_b, nullptr, pv, M, Ee, Ee);

        // build unfolded operands
        {
            size_t n1 = (size_t)Bb * Hh * Ss * Ff;
            size_t n2 = (size_t)Bb * Hh * SKk * Ff;
            size_t n3 = (size_t)Bb * Hh * SKk * DHh;
            k_build_qu<<<(unsigned)((n1 + 255) / 256), 256>>>();
            k_build_ku<<<(unsigned)((n2 + 255) / 256), 256>>>();
            k_build_vs<<<(unsigned)((n3 + 255) / 256), 256>>>();
        }

        // scores, softmax, AV
        dim3 gs((SKk + 63) / 64, Ss / 64, Bb * Hh);
        k_scores<<<gs, 256>>>();
        k_softmax<<<Bb * Hh * Ss, 256>>>();
        dim3 ga(1, Ss / 64, Bb * Hh);
        k_av<<<ga, 256>>>();

        // x = ln(attn)
        k_ln<<<M, 256>>>(pattn, ln_w, ln_b, px);

        // FFN with residual
        dim3 g1(HIDh / 64, M / 64);
        k_gemm<1, 0><<<g1, 256>>>(px, fc1_w, fc1_b, nullptr, phid, M, HIDh, Ee);
        dim3 g2(Ee / 64, M / 64);
        k_gemm<0, 1><<<g2, 256>>>(phid, fc2_w, fc2_b, px, pattn, M, Ee, HIDh);

        // x = ln(y)
        k_ln<<<M, 256>>>(pattn, ln_w, ln_b, px);
    }

    // output head
    dim3 go(CHUNKS, Bb);
    k_out_partial<<<go, 256>>>(out_w);
    k_out_final<<<Bb, 32>>>(out_b, out);
}

// round 2
// speedup vs baseline: 2.2978x; 2.2978x over previous
#include <cuda_runtime.h>
#include <math.h>
#include <stdint.h>

#define Bb 2
#define Ss 2048
#define Ee 512
#define Hh 8
#define DHh 64
#define Ww 5
#define PADp 2
#define SKk 2044
#define HIDh 2048
#define Ll 6
#define OUTo 6
#define SCALEc 0.125f
#define CHUNKS 128
#define SP 2048   // padded score/G column stride

// ---------------- scratch (static device globals; zero-initialized) ----------------
__device__ float g_x[Bb * Ss * Ee];
__device__ float g_q[Bb * Ss * Ee];
__device__ float g_k[Bb * Ss * Ee];
__device__ float g_v[Bb * Ss * Ee];
__device__ float g_G[(size_t)Bb * Hh * Ss * SP];   // 268 MB gram (pre-scaled)
__device__ float g_P[(size_t)Bb * Hh * Ss * SP];   // 268 MB softmax probs (cols >= SKk are 0)
__device__ float g_vs[(size_t)Bb * Hh * SP * DHh]; // window-summed V, rows >= SKk stay 0
__device__ float g_attn[Bb * Ss * Ee];
__device__ float g_hid[(size_t)Bb * Ss * HIDh];
__device__ float g_part[Bb * CHUNKS * OUTo];

// ---------------- tf32 helpers ----------------
__device__ __forceinline__ float2 tf32_split(float v) {
    uint32_t hi;
    asm("cvt.rna.tf32.f32 %0, %1;" : "=r"(hi) : "f"(v));
    float hf = __uint_as_float(hi);
    float r = v - hf;
    uint32_t lo;
    asm("cvt.rna.tf32.f32 %0, %1;" : "=r"(lo) : "f"(r));
    return make_float2(hf, __uint_as_float(lo));
}

__device__ __forceinline__ void mma8(float c[4], uint32_t a0, uint32_t a1, uint32_t a2,
                                     uint32_t a3, uint32_t b0, uint32_t b1) {
    asm volatile(
        "mma.sync.aligned.m16n8k8.row.col.f32.tf32.tf32.f32 "
        "{%0,%1,%2,%3},{%4,%5,%6,%7},{%8,%9},{%0,%1,%2,%3};"
        : "+f"(c[0]), "+f"(c[1]), "+f"(c[2]), "+f"(c[3])
        : "r"(a0), "r"(a1), "r"(a2), "r"(a3), "r"(b0), "r"(b1));
}

#define ASW 136   // 128 + 8: stride mod 16 == 8 -> perfect 2-phase LDS.64
#define BSW 72    // 64 + 8

// one BK=16 chunk of 3xTF32 mma. As[k][m], Bs[k][n], hi in .x, lo in .y
__device__ __forceinline__ void mma_chunk(const float2 (*As)[ASW], const float2 (*Bs)[BSW],
                                          int wm, int wn, int lane, float acc[2][4][4]) {
    int g = lane >> 2, tg = lane & 3;
#pragma unroll
    for (int ks = 0; ks < 2; ks++) {
        uint32_t ah[2][4], al[2][4];
#pragma unroll
        for (int mi = 0; mi < 2; mi++) {
            int m = wm * 32 + mi * 16 + g;
            float2 f0 = As[ks * 8 + tg][m];
            float2 f1 = As[ks * 8 + tg][m + 8];
            float2 f2 = As[ks * 8 + tg + 4][m];
            float2 f3 = As[ks * 8 + tg + 4][m + 8];
            ah[mi][0] = __float_as_uint(f0.x); al[mi][0] = __float_as_uint(f0.y);
            ah[mi][1] = __float_as_uint(f1.x); al[mi][1] = __float_as_uint(f1.y);
            ah[mi][2] = __float_as_uint(f2.x); al[mi][2] = __float_as_uint(f2.y);
            ah[mi][3] = __float_as_uint(f3.x); al[mi][3] = __float_as_uint(f3.y);
        }
#pragma unroll
        for (int ni = 0; ni < 4; ni++) {
            int n = wn * 32 + ni * 8 + g;
            float2 e0 = Bs[ks * 8 + tg][n];
            float2 e1 = Bs[ks * 8 + tg + 4][n];
            uint32_t bh0 = __float_as_uint(e0.x), bl0 = __float_as_uint(e0.y);
            uint32_t bh1 = __float_as_uint(e1.x), bl1 = __float_as_uint(e1.y);
#pragma unroll
            for (int mi = 0; mi < 2; mi++) {
                mma8(acc[mi][ni], ah[mi][0], ah[mi][1], ah[mi][2], ah[mi][3], bh0, bh1);
                mma8(acc[mi][ni], ah[mi][0], ah[mi][1], ah[mi][2], ah[mi][3], bl0, bl1);
                mma8(acc[mi][ni], al[mi][0], al[mi][1], al[mi][2], al[mi][3], bh0, bh1);
            }
        }
    }
}

__device__ __forceinline__ void sstoreA(float2 (*As)[ASW], int kq, int row, float4 v) {
    As[kq + 0][row] = tf32_split(v.x);
    As[kq + 1][row] = tf32_split(v.y);
    As[kq + 2][row] = tf32_split(v.z);
    As[kq + 3][row] = tf32_split(v.w);
}
__device__ __forceinline__ void sstoreBrow(float2 (*Bs)[BSW], int k, int n, float4 v) {
    Bs[k][n + 0] = tf32_split(v.x);
    Bs[k][n + 1] = tf32_split(v.y);
    Bs[k][n + 2] = tf32_split(v.z);
    Bs[k][n + 3] = tf32_split(v.w);
}
__device__ __forceinline__ void sstoreBcol(float2 (*Bs)[BSW], int k, int n, float4 v) {
    Bs[k + 0][n] = tf32_split(v.x);
    Bs[k + 1][n] = tf32_split(v.y);
    Bs[k + 2][n] = tf32_split(v.z);
    Bs[k + 3][n] = tf32_split(v.w);
}

// ---------------- embedding + positional encoding ----------------
__global__ void k_embed(const int* __restrict__ inp, const float* __restrict__ emb) {
    int idx = blockIdx.x * blockDim.x + threadIdx.x;
    if (idx >= Bb * Ss * Ee) return;
    int e = idx % Ee;
    int bs = idx / Ee;
    int s = bs % Ss;
    int tok = inp[bs];
    const float LN1E4 = 9.210340371976184f;
    int ebase = e & ~1;
    float freq = expf(-(float)ebase * (LN1E4 / (float)Ee));
    float ang = (float)s * freq;
    float pe = (e & 1) ? cosf(ang) : sinf(ang);
    g_x[idx] = emb[(size_t)tok * Ee + e] + pe;
}

// ---------------- generic mma GEMM: C[M,N] = A[M,K] @ W[K,N] + bias (+res)(+relu) ----
// M%128==0, N%64==0, K%16==0
template <int RELU, int RES>
__launch_bounds__(256)
__global__ void k_mm(const float* __restrict__ A, const float* __restrict__ W,
                     const float* __restrict__ bias, const float* __restrict__ res,
                     float* __restrict__ C, int M, int N, int K) {
    __shared__ float2 As[16][ASW];
    __shared__ float2 Bs[16][BSW];
    int t = threadIdx.x, lane = t & 31, wid = t >> 5;
    int wm = wid & 3, wn = wid >> 2;
    int bm = blockIdx.y * 128, bn = blockIdx.x * 64;
    float acc[2][4][4] = {};

    int rowA0 = t >> 2, kqA = (t & 3) << 2;
    int rowA1 = rowA0 + 64;
    int krB = t >> 4, nqB = (t & 15) << 2;

    float4 va0 = *(const float4*)(A + (size_t)(bm + rowA0) * K + kqA);
    float4 va1 = *(const float4*)(A + (size_t)(bm + rowA1) * K + kqA);
    float4 vb  = *(const float4*)(W + (size_t)krB * N + bn + nqB);

    for (int k0 = 0; k0 < K; k0 += 16) {
        sstoreA(As, kqA, rowA0, va0);
        sstoreA(As, kqA, rowA1, va1);
        sstoreBrow(Bs, krB, nqB, vb);
        __syncthreads();
        if (k0 + 16 < K) {
            va0 = *(const float4*)(A + (size_t)(bm + rowA0) * K + k0 + 16 + kqA);
            va1 = *(const float4*)(A + (size_t)(bm + rowA1) * K + k0 + 16 + kqA);
            vb  = *(const float4*)(W + (size_t)(k0 + 16 + krB) * N + bn + nqB);
        }
        mma_chunk(As, Bs, wm, wn, lane, acc);
        __syncthreads();
    }

    int g = lane >> 2, tg = lane & 3;
#pragma unroll
    for (int mi = 0; mi < 2; mi++)
#pragma unroll
        for (int ni = 0; ni < 4; ni++) {
            int r0 = bm + wm * 32 + mi * 16 + g;
            int c0 = bn + wn * 32 + ni * 8 + 2 * tg;
            float bv0 = bias[c0], bv1 = bias[c0 + 1];
            float v00 = acc[mi][ni][0] + bv0;
            float v01 = acc[mi][ni][1] + bv1;
            float v10 = acc[mi][ni][2] + bv0;
            float v11 = acc[mi][ni][3] + bv1;
            if (RES) {
                v00 += res[(size_t)r0 * N + c0];
                v01 += res[(size_t)r0 * N + c0 + 1];
                v10 += res[(size_t)(r0 + 8) * N + c0];
                v11 += res[(size_t)(r0 + 8) * N + c0 + 1];
            }
            if (RELU) {
                v00 = fmaxf(v00, 0.f); v01 = fmaxf(v01, 0.f);
                v10 = fmaxf(v10, 0.f); v11 = fmaxf(v11, 0.f);
            }
            C[(size_t)r0 * N + c0] = v00;
            C[(size_t)r0 * N + c0 + 1] = v01;
            C[(size_t)(r0 + 8) * N + c0] = v10;
            C[(size_t)(r0 + 8) * N + c0 + 1] = v11;
        }
}

// ---------------- gram: G[bh][i][m] = SCALE * q_i . k_m  (NT, batched) ----------------
__launch_bounds__(256)
__global__ void k_gram(const float* __restrict__ Q, const float* __restrict__ Km) {
    int bh = blockIdx.z;
    int b = bh >> 3, h = bh & 7;
    const float* Ab = Q + (size_t)b * Ss * Ee + h * DHh;   // row i, stride Ee, 64 cols
    const float* Kb = Km + (size_t)b * Ss * Ee + h * DHh;  // row m, stride Ee
    float* C = g_G + (size_t)bh * Ss * SP;

    __shared__ float2 As[16][ASW];
    __shared__ float2 Bs[16][BSW];
    int t = threadIdx.x, lane = t & 31, wid = t >> 5;
    int wm = wid & 3, wn = wid >> 2;
    int bm = blockIdx.y * 128, bn = blockIdx.x * 64;
    float acc[2][4][4] = {};

    int rowA0 = t >> 2, kqA = (t & 3) << 2;
    int rowA1 = rowA0 + 64;
    int mB = t >> 2, dqB = (t & 3) << 2;

    float4 va0 = *(const float4*)(Ab + (size_t)(bm + rowA0) * Ee + kqA);
    float4 va1 = *(const float4*)(Ab + (size_t)(bm + rowA1) * Ee + kqA);
    float4 vb  = *(const float4*)(Kb + (size_t)(bn + mB) * Ee + dqB);

    for (int k0 = 0; k0 < DHh; k0 += 16) {
        sstoreA(As, kqA, rowA0, va0);
        sstoreA(As, kqA, rowA1, va1);
        sstoreBcol(Bs, dqB, mB, vb);
        __syncthreads();
        if (k0 + 16 < DHh) {
            va0 = *(const float4*)(Ab + (size_t)(bm + rowA0) * Ee + k0 + 16 + kqA);
            va1 = *(const float4*)(Ab + (size_t)(bm + rowA1) * Ee + k0 + 16 + kqA);
            vb  = *(const float4*)(Kb + (size_t)(bn + mB) * Ee + k0 + 16 + dqB);
        }
        mma_chunk(As, Bs, wm, wn, lane, acc);
        __syncthreads();
    }

    int g = lane >> 2, tg = lane & 3;
#pragma unroll
    for (int mi = 0; mi < 2; mi++)
#pragma unroll
        for (int ni = 0; ni < 4; ni++) {
            int r0 = bm + wm * 32 + mi * 16 + g;
            int c0 = bn + wn * 32 + ni * 8 + 2 * tg;
            C[(size_t)r0 * SP + c0]           = acc[mi][ni][0] * SCALEc;
            C[(size_t)r0 * SP + c0 + 1]       = acc[mi][ni][1] * SCALEc;
            C[(size_t)(r0 + 8) * SP + c0]     = acc[mi][ni][2] * SCALEc;
            C[(size_t)(r0 + 8) * SP + c0 + 1] = acc[mi][ni][3] * SCALEc;
        }
}

// ---------------- window-summed V (padded rows stay zero) ----------------
__global__ void k_build_vs(const float* __restrict__ V) {
    size_t idx = (size_t)blockIdx.x * blockDim.x + threadIdx.x;
    if (idx >= (size_t)Bb * Hh * SKk * DHh) return;
    int d = (int)(idx & 63);
    int k = (int)((idx >> 6) % SKk);
    int bh = (int)(idx / ((size_t)64 * SKk));
    int b = bh >> 3, h = bh & 7;
    float s = 0.f;
#pragma unroll
    for (int j = 0; j < Ww; j++)
        s += V[((size_t)b * Ss + k + j) * Ee + h * DHh + d];
    g_vs[((size_t)bh * SP + k) * DHh + d] = s;
}

// ---------------- shift-sum scores + softmax -> P ----------------
__launch_bounds__(256)
__global__ void k_softmax_shift() {
    int q = blockIdx.x & (Ss - 1);
    int bh = blockIdx.x >> 11;
    const float* Gb = g_G + (size_t)bh * Ss * SP;
    float* Pr = g_P + ((size_t)bh * Ss + q) * SP;
    int t = threadIdx.x;
    __shared__ float red[256];
    float sv[8];
    float mx = -1e30f;
#pragma unroll
    for (int it = 0; it < 8; it++) {
        int k = t + it * 256;
        float s = -1e30f;
        if (k < SKk) {
            s = 0.f;
#pragma unroll
            for (int j = 0; j < Ww; j++) {
                int i = q + j - PADp;
                if (i >= 0 && i < Ss) s += Gb[(size_t)i * SP + k + j];
            }
        }
        sv[it] = s;
        mx = fmaxf(mx, s);
    }
    red[t] = mx; __syncthreads();
    for (int off = 128; off > 0; off >>= 1) {
        if (t < off) red[t] = fmaxf(red[t], red[t + off]);
        __syncthreads();
    }
    mx = red[0]; __syncthreads();
    float sum = 0.f;
    float ev[8];
#pragma unroll
    for (int it = 0; it < 8; it++) {
        int k = t + it * 256;
        float e = (k < SKk) ? expf(sv[it] - mx) : 0.f;
        ev[it] = e;
        sum += e;
    }
    red[t] = sum; __syncthreads();
    for (int off = 128; off > 0; off >>= 1) {
        if (t < off) red[t] += red[t + off];
        __syncthreads();
    }
    float inv = 1.f / red[0];
#pragma unroll
    for (int it = 0; it < 8; it++) Pr[t + it * 256] = ev[it] * inv;
}

// ---------------- O = P @ Vsum (batched, strided output into [B,S,E]) ----------------
__launch_bounds__(256)
__global__ void k_av() {
    int bh = blockIdx.z;
    int b = bh >> 3, h = bh & 7;
    const float* A = g_P + (size_t)bh * Ss * SP;        // [2048, 2048]
    const float* Bv = g_vs + (size_t)bh * SP * DHh;     // [2048, 64]
    float* C = g_attn + (size_t)b * Ss * Ee + h * DHh;  // ldc = Ee

    __shared__ float2 As[16][ASW];
    __shared__ float2 Bs[16][BSW];
    int t = threadIdx.x, lane = t & 31, wid = t >> 5;
    int wm = wid & 3, wn = wid >> 2;
    int bm = blockIdx.y * 128;
    float acc[2][4][4] = {};

    int rowA0 = t >> 2, kqA = (t & 3) << 2;
    int rowA1 = rowA0 + 64;
    int krB = t >> 4, nqB = (t & 15) << 2;

    float4 va0 = *(const float4*)(A + (size_t)(bm + rowA0) * SP + kqA);
    float4 va1 = *(const float4*)(A + (size_t)(bm + rowA1) * SP + kqA);
    float4 vb  = *(const float4*)(Bv + (size_t)krB * DHh + nqB);

    for (int k0 = 0; k0 < SP; k0 += 16) {
        sstoreA(As, kqA, rowA0, va0);
        sstoreA(As, kqA, rowA1, va1);
        sstoreBrow(Bs, krB, nqB, vb);
        __syncthreads();
        if (k0 + 16 < SP) {
            va0 = *(const float4*)(A + (size_t)(bm + rowA0) * SP + k0 + 16 + kqA);
            va1 = *(const float4*)(A + (size_t)(bm + rowA1) * SP + k0 + 16 + kqA);
            vb  = *(const float4*)(Bv + (size_t)(k0 + 16 + krB) * DHh + nqB);
        }
        mma_chunk(As, Bs, wm, wn, lane, acc);
        __syncthreads();
    }

    int g = lane >> 2, tg = lane & 3;
#pragma unroll
    for (int mi = 0; mi < 2; mi++)
#pragma unroll
        for (int ni = 0; ni < 4; ni++) {
            int r0 = bm + wm * 32 + mi * 16 + g;
            int c0 = wn * 32 + ni * 8 + 2 * tg;
            C[(size_t)r0 * Ee + c0]           = acc[mi][ni][0];
            C[(size_t)r0 * Ee + c0 + 1]       = acc[mi][ni][1];
            C[(size_t)(r0 + 8) * Ee + c0]     = acc[mi][ni][2];
            C[(size_t)(r0 + 8) * Ee + c0 + 1] = acc[mi][ni][3];
        }
}

// ---------------- LayerNorm over last dim E ----------------
__launch_bounds__(256)
__global__ void k_ln(const float* __restrict__ in, const float* __restrict__ w,
                     const float* __restrict__ bz, float* __restrict__ out) {
    int row = blockIdx.x;
    const float* x = in + (size_t)row * Ee;
    __shared__ float red[256];
    int t = threadIdx.x;
    float s = 0.f;
    for (int i = t; i < Ee; i += 256) s += x[i];
    red[t] = s; __syncthreads();
    for (int off = 128; off > 0; off >>= 1) {
        if (t < off) red[t] += red[t + off];
        __syncthreads();
    }
    float m = red[0] * (1.0f / Ee);
    __syncthreads();
    float vs = 0.f;
    for (int i = t; i < Ee; i += 256) { float d = x[i] - m; vs += d * d; }
    red[t] = vs; __syncthreads();
    for (int off = 128; off > 0; off >>= 1) {
        if (t < off) red[t] += red[t + off];
        __syncthreads();
    }
    float var = red[0] * (1.0f / Ee);
    float inv = rsqrtf(var + 1e-5f);
    for (int i = t; i < Ee; i += 256)
        out[(size_t)row * Ee + i] = (x[i] - m) * inv * w[i] + bz[i];
}

// ---------------- output head ----------------
__launch_bounds__(256)
__global__ void k_out_partial(const float* __restrict__ ow) {
    int b = blockIdx.y, c = blockIdx.x;
    const int per = (Ss * Ee) / CHUNKS;
    const float* x = g_x + (size_t)b * Ss * Ee + (size_t)c * per;
    const float* wr = ow + (size_t)c * per * OUTo;
    int t = threadIdx.x;
    float acc[OUTo] = {};
    for (int i = t; i < per; i += 256) {
        float xv = x[i];
#pragma unroll
        for (int o = 0; o < OUTo; o++) acc[o] = fmaf(xv, wr[(size_t)i * OUTo + o], acc[o]);
    }
    __shared__ float red[256 * OUTo];
#pragma unroll
    for (int o = 0; o < OUTo; o++) red[t * OUTo + o] = acc[o];
    __syncthreads();
    for (int off = 128; off > 0; off >>= 1) {
        if (t < off) {
#pragma unroll
            for (int o = 0; o < OUTo; o++)
                red[t * OUTo + o] += red[(t + off) * OUTo + o];
        }
        __syncthreads();
    }
    if (t == 0) {
#pragma unroll
        for (int o = 0; o < OUTo; o++)
            g_part[((size_t)b * CHUNKS + c) * OUTo + o] = red[o];
    }
}

__global__ void k_out_final(const float* __restrict__ ob, float* __restrict__ out) {
    int b = blockIdx.x;
    int o = threadIdx.x;
    if (o < OUTo) {
        float s = ob[o];
        for (int c = 0; c < CHUNKS; c++) s += g_part[(b * CHUNKS + c) * OUTo + o];
        out[b * OUTo + o] = s;
    }
}

// ---------------- host launcher ----------------
extern "C" void kernel_launch(void* const* d_in, const int* in_sizes, int n_in,
                              void* d_out, int out_size) {
    const int*   inputs = (const int*)d_in[0];
    const float* emb    = (const float*)d_in[1];
    const float* ln_w   = (const float*)d_in[2];
    const float* ln_b   = (const float*)d_in[3];
    const float* q_w    = (const float*)d_in[4];
    const float* q_b    = (const float*)d_in[5];
    const float* k_w    = (const float*)d_in[6];
    const float* k_b    = (const float*)d_in[7];
    const float* v_w    = (const float*)d_in[8];
    const float* v_b    = (const float*)d_in[9];
    const float* fc1_w  = (const float*)d_in[10];
    const float* fc1_b  = (const float*)d_in[11];
    const float* fc2_w  = (const float*)d_in[12];
    const float* fc2_b  = (const float*)d_in[13];
    const float* out_w  = (const float*)d_in[14];
    const float* out_b  = (const float*)d_in[15];
    float* out = (float*)d_out;

    float *px, *pq, *pk, *pv, *pattn, *phid;
    cudaGetSymbolAddress((void**)&px,    g_x);
    cudaGetSymbolAddress((void**)&pq,    g_q);
    cudaGetSymbolAddress((void**)&pk,    g_k);
    cudaGetSymbolAddress((void**)&pv,    g_v);
    cudaGetSymbolAddress((void**)&pattn, g_attn);
    cudaGetSymbolAddress((void**)&phid,  g_hid);

    const int M = Bb * Ss;  // 4096

    k_embed<<<(Bb * Ss * Ee + 255) / 256, 256>>>(inputs, emb);

    for (int l = 0; l < Ll; l++) {
        // QKV projections (tf32x3 mma)
        dim3 gq(Ee / 64, M / 128);
        k_mm<0, 0><<<gq, 256>>>(px, q_w, q_b, nullptr, pq, M, Ee, Ee);
        k_mm<0, 0><<<gq, 256>>>(px, k_w, k_b, nullptr, pk, M, Ee, Ee);
        k_mm<0, 0><<<gq, 256>>>(px, v_w, v_b, nullptr, pv, M, Ee, Ee);

        // window-summed V
        {
            size_t n3 = (size_t)Bb * Hh * SKk * DHh;
            k_build_vs<<<(unsigned)((n3 + 255) / 256), 256>>>(pv);
        }

        // gram, shift-softmax, AV
        dim3 gg(Ss / 64, Ss / 128, Bb * Hh);
        k_gram<<<gg, 256>>>(pq, pk);
        k_softmax_shift<<<Bb * Hh * Ss, 256>>>();
        dim3 ga(1, Ss / 128, Bb * Hh);
        k_av<<<ga, 256>>>();

        // x = ln(attn)
        k_ln<<<M, 256>>>(pattn, ln_w, ln_b, px);

        // FFN with residual
        dim3 g1(HIDh / 64, M / 128);
        k_mm<1, 0><<<g1, 256>>>(px, fc1_w, fc1_b, nullptr, phid, M, HIDh, Ee);
        dim3 g2(Ee / 64, M / 128);
        k_mm<0, 1><<<g2, 256>>>(phid, fc2_w, fc2_b, px, pattn, M, Ee, HIDh);

        // x = ln(y)
        k_ln<<<M, 256>>>(pattn, ln_w, ln_b, px);
    }

    dim3 go(CHUNKS, Bb);
    k_out_partial<<<go, 256>>>(out_w);
    k_out_final<<<Bb, 32>>>(out_b, out);
}

// round 3
// speedup vs baseline: 3.5192x; 1.5316x over previous
#include <cuda_runtime.h>
#include <cuda_bf16.h>
#include <math.h>
#include <stdint.h>

#define Bb 2
#define Ss 2048
#define Ee 512
#define Hh 8
#define DHh 64
#define Ww 5
#define PADp 2
#define SKk 2044
#define HIDh 2048
#define Ll 6
#define OUTo 6
#define SCALEc 0.125f
#define CHUNKS 128
#define SP 2048   // padded score/G column stride

#define AST 132   // A stage row stride in uint2 words (128 + 4): 132 % 16 == 4
#define BST 68    // B stage row stride in uint2 words (64 + 4):  68 % 16 == 4

// ---------------- scratch (static device globals; zero-initialized) ----------------
__device__ float g_x[Bb * Ss * Ee];
__device__ float g_q[Bb * Ss * Ee];
__device__ float g_k[Bb * Ss * Ee];
__device__ float g_v[Bb * Ss * Ee];
__device__ float g_G[(size_t)Bb * Hh * Ss * SP];   // gram (pre-scaled)
__device__ float g_P[(size_t)Bb * Hh * Ss * SP];   // softmax probs (cols >= SKk are 0)
__device__ float g_vs[(size_t)Bb * Hh * SP * DHh]; // window-summed V, rows >= SKk stay 0
__device__ float g_attn[Bb * Ss * Ee];
__device__ float g_hid[(size_t)Bb * Ss * HIDh];
__device__ float g_part[Bb * CHUNKS * OUTo];

// ---------------- bf16 split/pack: word = (hi pair, lo pair) of 2 consecutive k ----
__device__ __forceinline__ uint2 sp2(float x, float y) {
    __nv_bfloat16 xh = __float2bfloat16_rn(x);
    __nv_bfloat16 yh = __float2bfloat16_rn(y);
    float xr = x - __bfloat162float(xh);
    float yr = y - __bfloat162float(yh);
    __nv_bfloat16 xl = __float2bfloat16_rn(xr);
    __nv_bfloat16 yl = __float2bfloat16_rn(yr);
    uint2 w;
    w.x = ((uint32_t)__bfloat16_as_ushort(yh) << 16) | (uint32_t)__bfloat16_as_ushort(xh);
    w.y = ((uint32_t)__bfloat16_as_ushort(yl) << 16) | (uint32_t)__bfloat16_as_ushort(xl);
    return w;
}

__device__ __forceinline__ void mma16(float c[4], uint32_t a0, uint32_t a1, uint32_t a2,
                                      uint32_t a3, uint32_t b0, uint32_t b1) {
    asm volatile(
        "mma.sync.aligned.m16n8k16.row.col.f32.bf16.bf16.f32 "
        "{%0,%1,%2,%3},{%4,%5,%6,%7},{%8,%9},{%0,%1,%2,%3};"
        : "+f"(c[0]), "+f"(c[1]), "+f"(c[2]), "+f"(c[3])
        : "r"(a0), "r"(a1), "r"(a2), "r"(a3), "r"(b0), "r"(b1));
}

// one 16-k chunk of bf16x3 mma over a 128x64 block tile (warp tile 32x32)
__device__ __forceinline__ void mma_chunk(const uint2* sA, const uint2* sB,
                                          int wm, int wn, int lane, float acc[2][4][4]) {
    int g = lane >> 2, tg = lane & 3;
    uint32_t ah[2][4], al[2][4];
#pragma unroll
    for (int mi = 0; mi < 2; mi++) {
        int m = wm * 32 + mi * 16 + g;
        uint2 u0 = sA[(size_t)tg * AST + m];
        uint2 u1 = sA[(size_t)tg * AST + m + 8];
        uint2 u2 = sA[(size_t)(tg + 4) * AST + m];
        uint2 u3 = sA[(size_t)(tg + 4) * AST + m + 8];
        ah[mi][0] = u0.x; al[mi][0] = u0.y;
        ah[mi][1] = u1.x; al[mi][1] = u1.y;
        ah[mi][2] = u2.x; al[mi][2] = u2.y;
        ah[mi][3] = u3.x; al[mi][3] = u3.y;
    }
#pragma unroll
    for (int ni = 0; ni < 4; ni++) {
        int n = wn * 32 + ni * 8 + g;
        uint2 v0 = sB[(size_t)tg * BST + n];
        uint2 v1 = sB[(size_t)(tg + 4) * BST + n];
#pragma unroll
        for (int mi = 0; mi < 2; mi++) {
            mma16(acc[mi][ni], ah[mi][0], ah[mi][1], ah[mi][2], ah[mi][3], v0.x, v1.x);
            mma16(acc[mi][ni], ah[mi][0], ah[mi][1], ah[mi][2], ah[mi][3], v0.y, v1.y);
            mma16(acc[mi][ni], al[mi][0], al[mi][1], al[mi][2], al[mi][3], v0.x, v1.x);
        }
    }
}

// ---------------- unified GEMM core -------------------------------------------------
// C[128 x 64 tile at (bm, bn)] = A[M,K](lda) @ B (+bias)(+res)(relu)(scale)
// BT=0: B is [K,N] row-major (ldb = row stride). BT=1: B is [N,K] row-major (ldb).
template <int BT, int BIAS, int RELU, int RES, int SCL>
__device__ __forceinline__ void gemm_core(
    const float* __restrict__ A, const float* __restrict__ B,
    const float* __restrict__ bias, const float* __restrict__ res,
    float* __restrict__ C, int K, int lda, int ldb, int ldc,
    int bm, int bn) {
    __shared__ uint2 sA[2][8 * AST];
    __shared__ uint2 sB[2][8 * BST];

    int t = threadIdx.x, lane = t & 31, wid = t >> 5;
    int wm = wid & 3, wn = wid >> 2;
    float acc[2][4][4] = {};

    // A loader: mA = t&127, koA = (t>>7)*8  (two float4 per chunk)
    int mA = t & 127, koA = (t >> 7) * 8;
    const float* Arow = A + (size_t)(bm + mA) * lda + koA;
    // B loader
    int kpB = t >> 5, nB = (t & 31) * 2;          // BT=0
    int nBT = t & 63, koBT = (t >> 6) * 4;        // BT=1
    const float* Bp0;
    const float* Bp1 = nullptr;
    if (BT == 0) {
        Bp0 = B + (size_t)(2 * kpB) * ldb + bn + nB;
        Bp1 = B + (size_t)(2 * kpB + 1) * ldb + bn + nB;
    } else {
        Bp0 = B + (size_t)(bn + nBT) * ldb + koBT;
    }

    float4 a0 = *(const float4*)(Arow);
    float4 a1 = *(const float4*)(Arow + 4);
    float2 b0, b1;
    float4 bt;
    if (BT == 0) {
        b0 = *(const float2*)(Bp0);
        b1 = *(const float2*)(Bp1);
    } else {
        bt = *(const float4*)(Bp0);
    }

    // store chunk 0 into stage 0
    {
        int kp0 = koA >> 1;
        uint2* pa = sA[0];
        pa[(size_t)(kp0 + 0) * AST + mA] = sp2(a0.x, a0.y);
        pa[(size_t)(kp0 + 1) * AST + mA] = sp2(a0.z, a0.w);
        pa[(size_t)(kp0 + 2) * AST + mA] = sp2(a1.x, a1.y);
        pa[(size_t)(kp0 + 3) * AST + mA] = sp2(a1.z, a1.w);
        uint2* pb = sB[0];
        if (BT == 0) {
            pb[(size_t)kpB * BST + nB]     = sp2(b0.x, b1.x);
            pb[(size_t)kpB * BST + nB + 1] = sp2(b0.y, b1.y);
        } else {
            int kp = koBT >> 1;
            pb[(size_t)(kp + 0) * BST + nBT] = sp2(bt.x, bt.y);
            pb[(size_t)(kp + 1) * BST + nBT] = sp2(bt.z, bt.w);
        }
    }
    __syncthreads();

    for (int k0 = 0; k0 < K; k0 += 16) {
        int s = (k0 >> 4) & 1;
        bool more = (k0 + 16 < K);
        if (more) {
            a0 = *(const float4*)(Arow + k0 + 16);
            a1 = *(const float4*)(Arow + k0 + 16 + 4);
            if (BT == 0) {
                b0 = *(const float2*)(Bp0 + (size_t)(k0 + 16) * ldb);
                b1 = *(const float2*)(Bp1 + (size_t)(k0 + 16) * ldb);
            } else {
                bt = *(const float4*)(Bp0 + k0 + 16);
            }
        }
        mma_chunk(sA[s], sB[s], wm, wn, lane, acc);
        if (more) {
            int s2 = s ^ 1;
            int kp0 = koA >> 1;
            uint2* pa = sA[s2];
            pa[(size_t)(kp0 + 0) * AST + mA] = sp2(a0.x, a0.y);
            pa[(size_t)(kp0 + 1) * AST + mA] = sp2(a0.z, a0.w);
            pa[(size_t)(kp0 + 2) * AST + mA] = sp2(a1.x, a1.y);
            pa[(size_t)(kp0 + 3) * AST + mA] = sp2(a1.z, a1.w);
            uint2* pb = sB[s2];
            if (BT == 0) {
                pb[(size_t)kpB * BST + nB]     = sp2(b0.x, b1.x);
                pb[(size_t)kpB * BST + nB + 1] = sp2(b0.y, b1.y);
            } else {
                int kp = koBT >> 1;
                pb[(size_t)(kp + 0) * BST + nBT] = sp2(bt.x, bt.y);
                pb[(size_t)(kp + 1) * BST + nBT] = sp2(bt.z, bt.w);
            }
        }
        __syncthreads();
    }

    int g = lane >> 2, tg = lane & 3;
#pragma unroll
    for (int mi = 0; mi < 2; mi++)
#pragma unroll
        for (int ni = 0; ni < 4; ni++) {
            int r0 = bm + wm * 32 + mi * 16 + g;
            int c0 = bn + wn * 32 + ni * 8 + 2 * tg;
            float v00 = acc[mi][ni][0];
            float v01 = acc[mi][ni][1];
            float v10 = acc[mi][ni][2];
            float v11 = acc[mi][ni][3];
            if (SCL) { v00 *= SCALEc; v01 *= SCALEc; v10 *= SCALEc; v11 *= SCALEc; }
            if (BIAS) {
                float bv0 = bias[c0], bv1 = bias[c0 + 1];
                v00 += bv0; v01 += bv1; v10 += bv0; v11 += bv1;
            }
            if (RES) {
                v00 += res[(size_t)r0 * ldc + c0];
                v01 += res[(size_t)r0 * ldc + c0 + 1];
                v10 += res[(size_t)(r0 + 8) * ldc + c0];
                v11 += res[(size_t)(r0 + 8) * ldc + c0 + 1];
            }
            if (RELU) {
                v00 = fmaxf(v00, 0.f); v01 = fmaxf(v01, 0.f);
                v10 = fmaxf(v10, 0.f); v11 = fmaxf(v11, 0.f);
            }
            C[(size_t)r0 * ldc + c0] = v00;
            C[(size_t)r0 * ldc + c0 + 1] = v01;
            C[(size_t)(r0 + 8) * ldc + c0] = v10;
            C[(size_t)(r0 + 8) * ldc + c0 + 1] = v11;
        }
}

// ---------------- kernel wrappers ----------------
template <int RELU, int RES>
__launch_bounds__(256)
__global__ void k_mm(const float* __restrict__ A, const float* __restrict__ W,
                     const float* __restrict__ bias, const float* __restrict__ res,
                     float* __restrict__ C, int N, int K) {
    gemm_core<0, 1, RELU, RES, 0>(A, W, bias, res, C, K, K, N, N,
                                  blockIdx.y * 128, blockIdx.x * 64);
}

__launch_bounds__(256)
__global__ void k_gram(const float* __restrict__ Q, const float* __restrict__ Km) {
    int bh = blockIdx.z;
    int b = bh >> 3, h = bh & 7;
    const float* Ab = Q + (size_t)b * Ss * Ee + h * DHh;
    const float* Kb = Km + (size_t)b * Ss * Ee + h * DHh;
    float* C = g_G + (size_t)bh * Ss * SP;
    gemm_core<1, 0, 0, 0, 1>(Ab, Kb, nullptr, nullptr, C, DHh, Ee, Ee, SP,
                             blockIdx.y * 128, blockIdx.x * 64);
}

__launch_bounds__(256)
__global__ void k_av() {
    int bh = blockIdx.z;
    int b = bh >> 3, h = bh & 7;
    const float* A = g_P + (size_t)bh * Ss * SP;
    const float* Bv = g_vs + (size_t)bh * SP * DHh;
    float* C = g_attn + (size_t)b * Ss * Ee + h * DHh;
    gemm_core<0, 0, 0, 0, 0>(A, Bv, nullptr, nullptr, C, SP, SP, DHh, Ee,
                             blockIdx.y * 128, 0);
}

// ---------------- embedding + positional encoding ----------------
__global__ void k_embed(const int* __restrict__ inp, const float* __restrict__ emb) {
    int idx = blockIdx.x * blockDim.x + threadIdx.x;
    if (idx >= Bb * Ss * Ee) return;
    int e = idx % Ee;
    int bs = idx / Ee;
    int s = bs % Ss;
    int tok = inp[bs];
    const float LN1E4 = 9.210340371976184f;
    int ebase = e & ~1;
    float freq = expf(-(float)ebase * (LN1E4 / (float)Ee));
    float ang = (float)s * freq;
    float pe = (e & 1) ? cosf(ang) : sinf(ang);
    g_x[idx] = emb[(size_t)tok * Ee + e] + pe;
}

// ---------------- window-summed V (padded rows stay zero) ----------------
__global__ void k_build_vs(const float* __restrict__ V) {
    size_t idx = (size_t)blockIdx.x * blockDim.x + threadIdx.x;
    if (idx >= (size_t)Bb * Hh * SKk * DHh) return;
    int d = (int)(idx & 63);
    int k = (int)((idx >> 6) % SKk);
    int bh = (int)(idx / ((size_t)64 * SKk));
    int b = bh >> 3, h = bh & 7;
    float s = 0.f;
#pragma unroll
    for (int j = 0; j < Ww; j++)
        s += V[((size_t)b * Ss + k + j) * Ee + h * DHh + d];
    g_vs[((size_t)bh * SP + k) * DHh + d] = s;
}

// ---------------- shift-sum scores + softmax -> P ----------------
__launch_bounds__(256)
__global__ void k_softmax_shift() {
    int q = blockIdx.x & (Ss - 1);
    int bh = blockIdx.x >> 11;
    const float* Gb = g_G + (size_t)bh * Ss * SP;
    float* Pr = g_P + ((size_t)bh * Ss + q) * SP;
    int t = threadIdx.x;
    __shared__ float red[256];
    float sv[8];
    float mx = -1e30f;
#pragma unroll
    for (int it = 0; it < 8; it++) {
        int k = t + it * 256;
        float s = -1e30f;
        if (k < SKk) {
            s = 0.f;
#pragma unroll
            for (int j = 0; j < Ww; j++) {
                int i = q + j - PADp;
                if (i >= 0 && i < Ss) s += Gb[(size_t)i * SP + k + j];
            }
        }
        sv[it] = s;
        mx = fmaxf(mx, s);
    }
    red[t] = mx; __syncthreads();
    for (int off = 128; off > 0; off >>= 1) {
        if (t < off) red[t] = fmaxf(red[t], red[t + off]);
        __syncthreads();
    }
    mx = red[0]; __syncthreads();
    float sum = 0.f;
    float ev[8];
#pragma unroll
    for (int it = 0; it < 8; it++) {
        int k = t + it * 256;
        float e = (k < SKk) ? expf(sv[it] - mx) : 0.f;
        ev[it] = e;
        sum += e;
    }
    red[t] = sum; __syncthreads();
    for (int off = 128; off > 0; off >>= 1) {
        if (t < off) red[t] += red[t + off];
        __syncthreads();
    }
    float inv = 1.f / red[0];
#pragma unroll
    for (int it = 0; it < 8; it++) Pr[t + it * 256] = ev[it] * inv;
}

// ---------------- LayerNorm over last dim E ----------------
__launch_bounds__(256)
__global__ void k_ln(const float* __restrict__ in, const float* __restrict__ w,
                     const float* __restrict__ bz, float* __restrict__ out) {
    int row = blockIdx.x;
    const float* x = in + (size_t)row * Ee;
    __shared__ float red[256];
    int t = threadIdx.x;
    float s = 0.f;
    for (int i = t; i < Ee; i += 256) s += x[i];
    red[t] = s; __syncthreads();
    for (int off = 128; off > 0; off >>= 1) {
        if (t < off) red[t] += red[t + off];
        __syncthreads();
    }
    float m = red[0] * (1.0f / Ee);
    __syncthreads();
    float vs = 0.f;
    for (int i = t; i < Ee; i += 256) { float d = x[i] - m; vs += d * d; }
    red[t] = vs; __syncthreads();
    for (int off = 128; off > 0; off >>= 1) {
        if (t < off) red[t] += red[t + off];
        __syncthreads();
    }
    float var = red[0] * (1.0f / Ee);
    float inv = rsqrtf(var + 1e-5f);
    for (int i = t; i < Ee; i += 256)
        out[(size_t)row * Ee + i] = (x[i] - m) * inv * w[i] + bz[i];
}

// ---------------- output head ----------------
__launch_bounds__(256)
__global__ void k_out_partial(const float* __restrict__ ow) {
    int b = blockIdx.y, c = blockIdx.x;
    const int per = (Ss * Ee) / CHUNKS;
    const float* x = g_x + (size_t)b * Ss * Ee + (size_t)c * per;
    const float* wr = ow + (size_t)c * per * OUTo;
    int t = threadIdx.x;
    float acc[OUTo] = {};
    for (int i = t; i < per; i += 256) {
        float xv = x[i];
#pragma unroll
        for (int o = 0; o < OUTo; o++) acc[o] = fmaf(xv, wr[(size_t)i * OUTo + o], acc[o]);
    }
    __shared__ float red[256 * OUTo];
#pragma unroll
    for (int o = 0; o < OUTo; o++) red[t * OUTo + o] = acc[o];
    __syncthreads();
    for (int off = 128; off > 0; off >>= 1) {
        if (t < off) {
#pragma unroll
            for (int o = 0; o < OUTo; o++)
                red[t * OUTo + o] += red[(t + off) * OUTo + o];
        }
        __syncthreads();
    }
    if (t == 0) {
#pragma unroll
        for (int o = 0; o < OUTo; o++)
            g_part[((size_t)b * CHUNKS + c) * OUTo + o] = red[o];
    }
}

__global__ void k_out_final(const float* __restrict__ ob, float* __restrict__ out) {
    int b = blockIdx.x;
    int o = threadIdx.x;
    if (o < OUTo) {
        float s = ob[o];
        for (int c = 0; c < CHUNKS; c++) s += g_part[(b * CHUNKS + c) * OUTo + o];
        out[b * OUTo + o] = s;
    }
}

// ---------------- host launcher ----------------
extern "C" void kernel_launch(void* const* d_in, const int* in_sizes, int n_in,
                              void* d_out, int out_size) {
    const int*   inputs = (const int*)d_in[0];
    const float* emb    = (const float*)d_in[1];
    const float* ln_w   = (const float*)d_in[2];
    const float* ln_b   = (const float*)d_in[3];
    const float* q_w    = (const float*)d_in[4];
    const float* q_b    = (const float*)d_in[5];
    const float* k_w    = (const float*)d_in[6];
    const float* k_b    = (const float*)d_in[7];
    const float* v_w    = (const float*)d_in[8];
    const float* v_b    = (const float*)d_in[9];
    const float* fc1_w  = (const float*)d_in[10];
    const float* fc1_b  = (const float*)d_in[11];
    const float* fc2_w  = (const float*)d_in[12];
    const float* fc2_b  = (const float*)d_in[13];
    const float* out_w  = (const float*)d_in[14];
    const float* out_b  = (const float*)d_in[15];
    float* out = (float*)d_out;

    float *px, *pq, *pk, *pv, *pattn, *phid;
    cudaGetSymbolAddress((void**)&px,    g_x);
    cudaGetSymbolAddress((void**)&pq,    g_q);
    cudaGetSymbolAddress((void**)&pk,    g_k);
    cudaGetSymbolAddress((void**)&pv,    g_v);
    cudaGetSymbolAddress((void**)&pattn, g_attn);
    cudaGetSymbolAddress((void**)&phid,  g_hid);

    const int M = Bb * Ss;  // 4096

    k_embed<<<(Bb * Ss * Ee + 255) / 256, 256>>>(inputs, emb);

    for (int l = 0; l < Ll; l++) {
        // QKV projections (bf16x3 mma)
        dim3 gq(Ee / 64, M / 128);
        k_mm<0, 0><<<gq, 256>>>(px, q_w, q_b, nullptr, pq, Ee, Ee);
        k_mm<0, 0><<<gq, 256>>>(px, k_w, k_b, nullptr, pk, Ee, Ee);
        k_mm<0, 0><<<gq, 256>>>(px, v_w, v_b, nullptr, pv, Ee, Ee);

        // window-summed V
        {
            size_t n3 = (size_t)Bb * Hh * SKk * DHh;
            k_build_vs<<<(unsigned)((n3 + 255) / 256), 256>>>(pv);
        }

        // gram, shift-softmax, AV
        dim3 gg(Ss / 64, Ss / 128, Bb * Hh);
        k_gram<<<gg, 256>>>(pq, pk);
        k_softmax_shift<<<Bb * Hh * Ss, 256>>>();
        dim3 ga(1, Ss / 128, Bb * Hh);
        k_av<<<ga, 256>>>();

        // x = ln(attn)
        k_ln<<<M, 256>>>(pattn, ln_w, ln_b, px);

        // FFN with residual
        dim3 g1(HIDh / 64, M / 128);
        k_mm<1, 0><<<g1, 256>>>(px, fc1_w, fc1_b, nullptr, phid, HIDh, Ee);
        dim3 g2(Ee / 64, M / 128);
        k_mm<0, 1><<<g2, 256>>>(phid, fc2_w, fc2_b, px, pattn, Ee, HIDh);

        // x = ln(y)
        k_ln<<<M, 256>>>(pattn, ln_w, ln_b, px);
    }

    dim3 go(CHUNKS, Bb);
    k_out_partial<<<go, 256>>>(out_w);
    k_out_final<<<Bb, 32>>>(out_b, out);
}

// round 4
// speedup vs baseline: 4.1460x; 1.1781x over previous
#include <cuda_runtime.h>
#include <cuda_bf16.h>
#include <math.h>
#include <stdint.h>

#define Bb 2
#define Ss 2048
#define Ee 512
#define Hh 8
#define DHh 64
#define Ww 5
#define PADp 2
#define SKk 2044
#define HIDh 2048
#define Ll 6
#define OUTo 6
#define SCALEc 0.125f
#define CHUNKS 128
#define SP 2048

#define AST 132   // smem A row stride in uint2
#define BST 68    // smem B row stride in uint2
#define GST 73    // flash G tile row stride in floats (72 used + 1; odd -> conflict-free)

// ---------------- scratch ----------------
__device__ float g_x[Bb * Ss * Ee];                      // fp32 activations (LN out)
__device__ uint2 g_xp[Bb * Ss * (Ee / 2)];               // packed activations
__device__ float g_qkv[Bb * Ss * 1536];                  // fp32 qkv
__device__ uint2 g_qkvp[Bb * Ss * 768];                  // packed qkv (pairs along n)
__device__ uint2 g_hidp[(size_t)Bb * Ss * (HIDh / 2)];   // packed fc1 out
__device__ float g_G[(size_t)Bb * Hh * Ss * SP + 128];   // gram, pre-scaled (+pad)
__device__ uint2 g_vsp[(size_t)Bb * Hh * (SP / 2) * DHh];// packed window-summed V (zeros beyond SKk)
__device__ float g_attn[Bb * Ss * Ee];
__device__ float g_part[Bb * CHUNKS * OUTo];
// packed weights
__device__ uint2 g_wqkv[(Ee / 2) * 1536];
__device__ float g_bqkv[1536];
__device__ uint2 g_wfc1[(Ee / 2) * HIDh];
__device__ uint2 g_wfc2[(HIDh / 2) * Ee];

// ---------------- bf16 split/pack ----------------
__device__ __forceinline__ uint2 sp2(float x, float y) {
    __nv_bfloat16 xh = __float2bfloat16_rn(x);
    __nv_bfloat16 yh = __float2bfloat16_rn(y);
    float xr = x - __bfloat162float(xh);
    float yr = y - __bfloat162float(yh);
    __nv_bfloat16 xl = __float2bfloat16_rn(xr);
    __nv_bfloat16 yl = __float2bfloat16_rn(yr);
    uint2 w;
    w.x = ((uint32_t)__bfloat16_as_ushort(yh) << 16) | (uint32_t)__bfloat16_as_ushort(xh);
    w.y = ((uint32_t)__bfloat16_as_ushort(yl) << 16) | (uint32_t)__bfloat16_as_ushort(xl);
    return w;
}

__device__ __forceinline__ void mma16(float c[4], uint32_t a0, uint32_t a1, uint32_t a2,
                                      uint32_t a3, uint32_t b0, uint32_t b1) {
    asm volatile(
        "mma.sync.aligned.m16n8k16.row.col.f32.bf16.bf16.f32 "
        "{%0,%1,%2,%3},{%4,%5,%6,%7},{%8,%9},{%0,%1,%2,%3};"
        : "+f"(c[0]), "+f"(c[1]), "+f"(c[2]), "+f"(c[3])
        : "r"(a0), "r"(a1), "r"(a2), "r"(a3), "r"(b0), "r"(b1));
}

// one 16-k chunk of bf16x3 mma over 128x64 tile (warp tile 32x32, 8 warps 4x2)
__device__ __forceinline__ void mma_chunk(const uint2* sA, const uint2* sB,
                                          int wm, int wn, int lane, float acc[2][4][4]) {
    int g = lane >> 2, tg = lane & 3;
    uint32_t ah[2][4], al[2][4];
#pragma unroll
    for (int mi = 0; mi < 2; mi++) {
        int m = wm * 32 + mi * 16 + g;
        uint2 u0 = sA[(size_t)tg * AST + m];
        uint2 u1 = sA[(size_t)tg * AST + m + 8];
        uint2 u2 = sA[(size_t)(tg + 4) * AST + m];
        uint2 u3 = sA[(size_t)(tg + 4) * AST + m + 8];
        ah[mi][0] = u0.x; al[mi][0] = u0.y;
        ah[mi][1] = u1.x; al[mi][1] = u1.y;
        ah[mi][2] = u2.x; al[mi][2] = u2.y;
        ah[mi][3] = u3.x; al[mi][3] = u3.y;
    }
#pragma unroll
    for (int ni = 0; ni < 4; ni++) {
        int n = wn * 32 + ni * 8 + g;
        uint2 v0 = sB[(size_t)tg * BST + n];
        uint2 v1 = sB[(size_t)(tg + 4) * BST + n];
#pragma unroll
        for (int mi = 0; mi < 2; mi++) {
            mma16(acc[mi][ni], ah[mi][0], ah[mi][1], ah[mi][2], ah[mi][3], v0.x, v1.x);
            mma16(acc[mi][ni], ah[mi][0], ah[mi][1], ah[mi][2], ah[mi][3], v0.y, v1.y);
            mma16(acc[mi][ni], al[mi][0], al[mi][1], al[mi][2], al[mi][3], v0.x, v1.x);
        }
    }
}

// ---------------- unified packed GEMM core ------------------------------------------
// A packed [M][lda2] uint2 (pairs along K). BT=0: B packed [K/2][ldb2]; BT=1: B packed [N][ldb2].
template <int BT, int BIAS, int RELU, int RES, int SCL, int WF32, int WPK>
__device__ __forceinline__ void gemm_core_p(
    const uint2* __restrict__ A, const uint2* __restrict__ B,
    const float* __restrict__ bias, const float* __restrict__ res,
    float* __restrict__ C, uint2* __restrict__ Cp,
    int K, int lda2, int ldb2, int ldc, int bm, int bn) {
    __shared__ uint2 sA[2][8 * AST];
    __shared__ uint2 sB[2][8 * BST];
    int t = threadIdx.x, lane = t & 31, wid = t >> 5;
    int wm = wid & 3, wn = wid >> 2;
    float acc[2][4][4] = {};

    int mA = t & 127, koA2 = (t >> 7) * 4;
    const uint2* Arow = A + (size_t)(bm + mA) * lda2 + koA2;

    int kpB = t >> 5, nB = (t & 31) * 2;
    int nBT = t & 63, kqBT = (t >> 6) * 2;
    const uint2* Bp = (BT == 0) ? (B + (size_t)kpB * ldb2 + bn + nB)
                                : (B + (size_t)(bn + nBT) * ldb2 + kqBT);

    uint4 a0 = *(const uint4*)(Arow);
    uint4 a1 = *(const uint4*)(Arow + 2);
    uint4 b0 = *(const uint4*)(Bp);

    // stage 0
    {
        uint2* pa = sA[0];
        pa[(size_t)(koA2 + 0) * AST + mA] = make_uint2(a0.x, a0.y);
        pa[(size_t)(koA2 + 1) * AST + mA] = make_uint2(a0.z, a0.w);
        pa[(size_t)(koA2 + 2) * AST + mA] = make_uint2(a1.x, a1.y);
        pa[(size_t)(koA2 + 3) * AST + mA] = make_uint2(a1.z, a1.w);
        uint2* pb = sB[0];
        if (BT == 0) {
            pb[(size_t)kpB * BST + nB]     = make_uint2(b0.x, b0.y);
            pb[(size_t)kpB * BST + nB + 1] = make_uint2(b0.z, b0.w);
        } else {
            pb[(size_t)(kqBT + 0) * BST + nBT] = make_uint2(b0.x, b0.y);
            pb[(size_t)(kqBT + 1) * BST + nBT] = make_uint2(b0.z, b0.w);
        }
    }
    __syncthreads();

    int nch = K >> 4;
    for (int ch = 0; ch < nch; ch++) {
        int s = ch & 1;
        bool more = (ch + 1 < nch);
        if (more) {
            int off = (ch + 1) * 8;
            a0 = *(const uint4*)(Arow + off);
            a1 = *(const uint4*)(Arow + off + 2);
            const uint2* Bn = (BT == 0) ? (Bp + (size_t)(ch + 1) * 8 * ldb2) : (Bp + off);
            b0 = *(const uint4*)(Bn);
        }
        mma_chunk(sA[s], sB[s], wm, wn, lane, acc);
        if (more) {
            int s2 = s ^ 1;
            uint2* pa = sA[s2];
            pa[(size_t)(koA2 + 0) * AST + mA] = make_uint2(a0.x, a0.y);
            pa[(size_t)(koA2 + 1) * AST + mA] = make_uint2(a0.z, a0.w);
            pa[(size_t)(koA2 + 2) * AST + mA] = make_uint2(a1.x, a1.y);
            pa[(size_t)(koA2 + 3) * AST + mA] = make_uint2(a1.z, a1.w);
            uint2* pb = sB[s2];
            if (BT == 0) {
                pb[(size_t)kpB * BST + nB]     = make_uint2(b0.x, b0.y);
                pb[(size_t)kpB * BST + nB + 1] = make_uint2(b0.z, b0.w);
            } else {
                pb[(size_t)(kqBT + 0) * BST + nBT] = make_uint2(b0.x, b0.y);
                pb[(size_t)(kqBT + 1) * BST + nBT] = make_uint2(b0.z, b0.w);
            }
        }
        __syncthreads();
    }

    int g = lane >> 2, tg = lane & 3;
#pragma unroll
    for (int mi = 0; mi < 2; mi++)
#pragma unroll
        for (int ni = 0; ni < 4; ni++) {
            int r0 = bm + wm * 32 + mi * 16 + g;
            int c0 = bn + wn * 32 + ni * 8 + 2 * tg;
            float v00 = acc[mi][ni][0], v01 = acc[mi][ni][1];
            float v10 = acc[mi][ni][2], v11 = acc[mi][ni][3];
            if (SCL) { v00 *= SCALEc; v01 *= SCALEc; v10 *= SCALEc; v11 *= SCALEc; }
            if (BIAS) {
                float bv0 = bias[c0], bv1 = bias[c0 + 1];
                v00 += bv0; v01 += bv1; v10 += bv0; v11 += bv1;
            }
            if (RES) {
                v00 += res[(size_t)r0 * ldc + c0];
                v01 += res[(size_t)r0 * ldc + c0 + 1];
                v10 += res[(size_t)(r0 + 8) * ldc + c0];
                v11 += res[(size_t)(r0 + 8) * ldc + c0 + 1];
            }
            if (RELU) {
                v00 = fmaxf(v00, 0.f); v01 = fmaxf(v01, 0.f);
                v10 = fmaxf(v10, 0.f); v11 = fmaxf(v11, 0.f);
            }
            if (WF32) {
                C[(size_t)r0 * ldc + c0] = v00;
                C[(size_t)r0 * ldc + c0 + 1] = v01;
                C[(size_t)(r0 + 8) * ldc + c0] = v10;
                C[(size_t)(r0 + 8) * ldc + c0 + 1] = v11;
            }
            if (WPK) {
                Cp[(size_t)r0 * (ldc >> 1) + (c0 >> 1)] = sp2(v00, v01);
                Cp[(size_t)(r0 + 8) * (ldc >> 1) + (c0 >> 1)] = sp2(v10, v11);
            }
        }
}

// ---------------- GEMM kernel wrappers ----------------
__launch_bounds__(256)
__global__ void k_qkv() {
    gemm_core_p<0, 1, 0, 0, 0, 1, 1>(g_xp, g_wqkv, g_bqkv, nullptr, g_qkv, g_qkvp,
                                     Ee, Ee / 2, 1536, 1536,
                                     blockIdx.y * 128, blockIdx.x * 64);
}

__launch_bounds__(256)
__global__ void k_fc1(const float* __restrict__ bias) {
    gemm_core_p<0, 1, 1, 0, 0, 0, 1>(g_xp, g_wfc1, bias, nullptr, nullptr, g_hidp,
                                     Ee, Ee / 2, HIDh, HIDh,
                                     blockIdx.y * 128, blockIdx.x * 64);
}

__launch_bounds__(256)
__global__ void k_fc2(const float* __restrict__ bias) {
    gemm_core_p<0, 1, 0, 1, 0, 1, 0>(g_hidp, g_wfc2, bias, g_x, g_attn, nullptr,
                                     HIDh, HIDh / 2, Ee, Ee,
                                     blockIdx.y * 128, blockIdx.x * 64);
}

__launch_bounds__(256)
__global__ void k_gram() {
    int bh = blockIdx.z;
    int b = bh >> 3, h = bh & 7;
    const uint2* Ab = g_qkvp + (size_t)b * Ss * 768 + h * 32;         // Q
    const uint2* Bk = g_qkvp + (size_t)b * Ss * 768 + 256 + h * 32;   // K
    float* C = g_G + (size_t)bh * Ss * SP;
    gemm_core_p<1, 0, 0, 0, 1, 1, 0>(Ab, Bk, nullptr, nullptr, C, nullptr,
                                     DHh, 768, 768, SP,
                                     blockIdx.y * 128, blockIdx.x * 64);
}

// ---------------- weight packing (once per call) ----------------
__global__ void k_pack_qkv(const float* __restrict__ qw, const float* __restrict__ kw,
                           const float* __restrict__ vw, const float* __restrict__ qb,
                           const float* __restrict__ kb, const float* __restrict__ vb) {
    int idx = blockIdx.x * 256 + threadIdx.x;
    if (idx < (Ee / 2) * 1536) {
        int n = idx % 1536, kp = idx / 1536;
        const float* W = (n < 512) ? qw : (n < 1024 ? kw : vw);
        int c = n & 511;
        g_wqkv[idx] = sp2(W[(size_t)(2 * kp) * 512 + c], W[(size_t)(2 * kp + 1) * 512 + c]);
    }
    if (idx < 1536)
        g_bqkv[idx] = (idx < 512) ? qb[idx] : (idx < 1024 ? kb[idx - 512] : vb[idx - 1024]);
}

__global__ void k_pack_w(const float* __restrict__ W, uint2* __restrict__ out, int Kp, int N) {
    int idx = blockIdx.x * 256 + threadIdx.x;
    if (idx >= Kp * N) return;
    int n = idx % N, kp = idx / N;
    out[idx] = sp2(W[(size_t)(2 * kp) * N + n], W[(size_t)(2 * kp + 1) * N + n]);
}

// ---------------- embedding + positional encoding (fp32 + packed) ----------------
__global__ void k_embed(const int* __restrict__ inp, const float* __restrict__ emb) {
    int idx = blockIdx.x * blockDim.x + threadIdx.x;   // B*S*(E/2)
    if (idx >= Bb * Ss * (Ee / 2)) return;
    int ep = idx % (Ee / 2);
    int bs = idx / (Ee / 2);
    int s = bs % Ss;
    int tok = inp[bs];
    int e0 = 2 * ep;
    const float LN1E4 = 9.210340371976184f;
    float freq = expf(-(float)e0 * (LN1E4 / (float)Ee));
    float ang = (float)s * freq;
    float x0 = emb[(size_t)tok * Ee + e0] + sinf(ang);
    float x1 = emb[(size_t)tok * Ee + e0 + 1] + cosf(ang);
    g_x[(size_t)bs * Ee + e0] = x0;
    g_x[(size_t)bs * Ee + e0 + 1] = x1;
    g_xp[(size_t)bs * (Ee / 2) + ep] = sp2(x0, x1);
}

// ---------------- window-summed V, packed pairs along k-rows ----------------
__global__ void k_build_vs() {
    int idx = blockIdx.x * blockDim.x + threadIdx.x;   // 16 * 1022 * 64
    if (idx >= Bb * Hh * (SKk / 2) * DHh) return;
    int d = idx & 63;
    int rest = idx >> 6;
    int kp = rest % (SKk / 2);
    int bh = rest / (SKk / 2);
    int b = bh >> 3, h = bh & 7;
    const float* Vp = g_qkv + (size_t)b * Ss * 1536 + 1024 + h * DHh + d;
    int k = 2 * kp;
    float v0 = Vp[(size_t)(k + 0) * 1536];
    float v1 = Vp[(size_t)(k + 1) * 1536];
    float v2 = Vp[(size_t)(k + 2) * 1536];
    float v3 = Vp[(size_t)(k + 3) * 1536];
    float v4 = Vp[(size_t)(k + 4) * 1536];
    float v5 = Vp[(size_t)(k + 5) * 1536];
    float s0 = v0 + v1 + v2 + v3 + v4;
    float s1 = v1 + v2 + v3 + v4 + v5;
    g_vsp[((size_t)bh * (SP / 2) + kp) * DHh + d] = sp2(s0, s1);
}

// ---------------- fused flash softmax + AV ----------------
// per (q-tile 128, bh): stream 64-wide k-tiles; scores from shifted G sums; online softmax;
// P packed in smem; O += P @ Vsum via bf16x3 mma. Normalize at end.
#define FSAV_SG   (132 * GST)                // floats
#define FSAV_OFF_P  38544                    // bytes (132*73*4, 16B aligned)
#define FSAV_OFF_V  (FSAV_OFF_P + 33792)     // 32*132*8
#define FSAV_OFF_M  (FSAV_OFF_V + 17408)     // 32*68*8
#define FSAV_SMEM   (FSAV_OFF_M + 512 * 3 + 1024 * 2)

__launch_bounds__(256)
__global__ void k_fsav() {
    extern __shared__ char dyn[];
    float* sG = (float*)dyn;
    uint2* sP = (uint2*)(dyn + FSAV_OFF_P);
    uint2* sV = (uint2*)(dyn + FSAV_OFF_V);
    float* sM = (float*)(dyn + FSAV_OFF_M);
    float* sL = sM + 128;
    float* sFac = sM + 256;
    float* sRedM = sM + 384;   // [2][128]
    float* sRedS = sM + 640;   // [2][128]

    int qt = blockIdx.x;
    int bh = blockIdx.y;
    int b = bh >> 3, h = bh & 7;
    int q0 = qt * 128;
    const float* Gb = g_G + (size_t)bh * Ss * SP;
    const uint2* Vb = g_vsp + (size_t)bh * (SP / 2) * DHh;

    int t = threadIdx.x, lane = t & 31, wid = t >> 5;
    int wm = wid & 3, wn = wid >> 2;
    int g = lane >> 2, tg = lane & 3;
    float acc[2][4][4] = {};

    if (t < 128) { sM[t] = -1e30f; sL[t] = 0.f; }

    int srow = t & 127, kh = t >> 7;

    for (int k0 = 0; k0 < SP; k0 += 64) {
        // load Vsum tile (32 kp x 64 d)
        {
            int kpB = t >> 5, dB = (t & 31) * 2;
#pragma unroll
            for (int r = 0; r < 4; r++) {
                int kp = r * 8 + kpB;
                uint4 v = *(const uint4*)(Vb + (size_t)((k0 >> 1) + kp) * DHh + dB);
                sV[(size_t)kp * BST + dB] = make_uint2(v.x, v.y);
                sV[(size_t)kp * BST + dB + 1] = make_uint2(v.z, v.w);
            }
        }
        // load G tile: rows q0-2..q0+129, cols k0..k0+71
        for (int i = t; i < 132 * 18; i += 256) {
            int r = i / 18, c4 = i % 18;
            int gr = q0 - 2 + r;
            float4 v = make_float4(0.f, 0.f, 0.f, 0.f);
            if (gr >= 0 && gr < Ss)
                v = *(const float4*)(Gb + (size_t)gr * SP + k0 + c4 * 4);
            int base = r * GST + c4 * 4;
            sG[base] = v.x; sG[base + 1] = v.y; sG[base + 2] = v.z; sG[base + 3] = v.w;
        }
        __syncthreads();

        // scores (each thread: one row, 32 consecutive k)
        float sv[32];
        float lmax = -1e30f;
        int kbase = kh * 32;
#pragma unroll
        for (int i = 0; i < 32; i++) {
            int kg = k0 + kbase + i;
            float s = -1e30f;
            if (kg < SKk) {
                s = 0.f;
#pragma unroll
                for (int j = 0; j < Ww; j++)
                    s += sG[(srow + j) * GST + kbase + i + j];
            }
            sv[i] = s;
            lmax = fmaxf(lmax, s);
        }
        sRedM[kh * 128 + srow] = lmax;
        __syncthreads();

        float mold = sM[srow];
        float mnew = fmaxf(mold, fmaxf(sRedM[srow], sRedM[128 + srow]));
        float lsum = 0.f;
#pragma unroll
        for (int i = 0; i < 32; i += 2) {
            float p0 = __expf(sv[i] - mnew);
            float p1 = __expf(sv[i + 1] - mnew);
            lsum += p0 + p1;
            sP[(size_t)(kh * 16 + (i >> 1)) * AST + srow] = sp2(p0, p1);
        }
        sRedS[kh * 128 + srow] = lsum;
        __syncthreads();

        if (kh == 0) {
            float fac = __expf(mold - mnew);
            sL[srow] = sL[srow] * fac + sRedS[srow] + sRedS[128 + srow];
            sM[srow] = mnew;
            sFac[srow] = fac;
        }
        __syncthreads();

        // rescale + MMA
        {
            float f0 = sFac[wm * 32 + g];
            float f1 = sFac[wm * 32 + g + 8];
            float f2 = sFac[wm * 32 + g + 16];
            float f3 = sFac[wm * 32 + g + 24];
#pragma unroll
            for (int ni = 0; ni < 4; ni++) {
                acc[0][ni][0] *= f0; acc[0][ni][1] *= f0;
                acc[0][ni][2] *= f1; acc[0][ni][3] *= f1;
                acc[1][ni][0] *= f2; acc[1][ni][1] *= f2;
                acc[1][ni][2] *= f3; acc[1][ni][3] *= f3;
            }
#pragma unroll
            for (int c = 0; c < 4; c++)
                mma_chunk(sP + (size_t)c * 8 * AST, sV + (size_t)c * 8 * BST, wm, wn, lane, acc);
        }
        __syncthreads();
    }

    float inv0 = 1.f / sL[wm * 32 + g];
    float inv1 = 1.f / sL[wm * 32 + g + 8];
    float inv2 = 1.f / sL[wm * 32 + g + 16];
    float inv3 = 1.f / sL[wm * 32 + g + 24];
    float* Cb = g_attn + (size_t)b * Ss * Ee + h * DHh;
#pragma unroll
    for (int mi = 0; mi < 2; mi++)
#pragma unroll
        for (int ni = 0; ni < 4; ni++) {
            int r0 = q0 + wm * 32 + mi * 16 + g;
            int c0 = wn * 32 + ni * 8 + 2 * tg;
            float i0 = mi ? inv2 : inv0;
            float i1 = mi ? inv3 : inv1;
            Cb[(size_t)r0 * Ee + c0] = acc[mi][ni][0] * i0;
            Cb[(size_t)r0 * Ee + c0 + 1] = acc[mi][ni][1] * i0;
            Cb[(size_t)(r0 + 8) * Ee + c0] = acc[mi][ni][2] * i1;
            Cb[(size_t)(r0 + 8) * Ee + c0 + 1] = acc[mi][ni][3] * i1;
        }
}

// ---------------- LayerNorm (fp32 + packed out) ----------------
__launch_bounds__(256)
__global__ void k_ln(const float* __restrict__ in, const float* __restrict__ w,
                     const float* __restrict__ bz, float* __restrict__ out,
                     uint2* __restrict__ outp) {
    int row = blockIdx.x;
    const float* x = in + (size_t)row * Ee;
    __shared__ float red[256];
    int t = threadIdx.x;
    float x0 = x[2 * t], x1 = x[2 * t + 1];
    red[t] = x0 + x1; __syncthreads();
    for (int off = 128; off > 0; off >>= 1) {
        if (t < off) red[t] += red[t + off];
        __syncthreads();
    }
    float m = red[0] * (1.0f / Ee);
    __syncthreads();
    float d0 = x0 - m, d1 = x1 - m;
    red[t] = d0 * d0 + d1 * d1; __syncthreads();
    for (int off = 128; off > 0; off >>= 1) {
        if (t < off) red[t] += red[t + off];
        __syncthreads();
    }
    float inv = rsqrtf(red[0] * (1.0f / Ee) + 1e-5f);
    float y0 = d0 * inv * w[2 * t] + bz[2 * t];
    float y1 = d1 * inv * w[2 * t + 1] + bz[2 * t + 1];
    out[(size_t)row * Ee + 2 * t] = y0;
    out[(size_t)row * Ee + 2 * t + 1] = y1;
    outp[(size_t)row * (Ee / 2) + t] = sp2(y0, y1);
}

// ---------------- output head ----------------
__launch_bounds__(256)
__global__ void k_out_partial(const float* __restrict__ ow) {
    int b = blockIdx.y, c = blockIdx.x;
    const int per = (Ss * Ee) / CHUNKS;
    const float* x = g_x + (size_t)b * Ss * Ee + (size_t)c * per;
    const float* wr = ow + (size_t)c * per * OUTo;
    int t = threadIdx.x;
    float acc[OUTo] = {};
    for (int i = t; i < per; i += 256) {
        float xv = x[i];
#pragma unroll
        for (int o = 0; o < OUTo; o++) acc[o] = fmaf(xv, wr[(size_t)i * OUTo + o], acc[o]);
    }
    __shared__ float red[256 * OUTo];
#pragma unroll
    for (int o = 0; o < OUTo; o++) red[t * OUTo + o] = acc[o];
    __syncthreads();
    for (int off = 128; off > 0; off >>= 1) {
        if (t < off) {
#pragma unroll
            for (int o = 0; o < OUTo; o++)
                red[t * OUTo + o] += red[(t + off) * OUTo + o];
        }
        __syncthreads();
    }
    if (t == 0) {
#pragma unroll
        for (int o = 0; o < OUTo; o++)
            g_part[((size_t)b * CHUNKS + c) * OUTo + o] = red[o];
    }
}

__global__ void k_out_final(const float* __restrict__ ob, float* __restrict__ out) {
    int b = blockIdx.x;
    int o = threadIdx.x;
    if (o < OUTo) {
        float s = ob[o];
        for (int c = 0; c < CHUNKS; c++) s += g_part[(b * CHUNKS + c) * OUTo + o];
        out[b * OUTo + o] = s;
    }
}

// ---------------- host launcher ----------------
extern "C" void kernel_launch(void* const* d_in, const int* in_sizes, int n_in,
                              void* d_out, int out_size) {
    const int*   inputs = (const int*)d_in[0];
    const float* emb    = (const float*)d_in[1];
    const float* ln_w   = (const float*)d_in[2];
    const float* ln_b   = (const float*)d_in[3];
    const float* q_w    = (const float*)d_in[4];
    const float* q_b    = (const float*)d_in[5];
    const float* k_w    = (const float*)d_in[6];
    const float* k_b    = (const float*)d_in[7];
    const float* v_w    = (const float*)d_in[8];
    const float* v_b    = (const float*)d_in[9];
    const float* fc1_w  = (const float*)d_in[10];
    const float* fc1_b  = (const float*)d_in[11];
    const float* fc2_w  = (const float*)d_in[12];
    const float* fc2_b  = (const float*)d_in[13];
    const float* out_w  = (const float*)d_in[14];
    const float* out_b  = (const float*)d_in[15];
    float* out = (float*)d_out;

    static int smem_set = 0;
    if (!smem_set) {
        cudaFuncSetAttribute(k_fsav, cudaFuncAttributeMaxDynamicSharedMemorySize, FSAV_SMEM);
        smem_set = 1;
    }

    float *pfc1w, *pfc2w;
    uint2 *pwfc1, *pwfc2;
    cudaGetSymbolAddress((void**)&pwfc1, g_wfc1);
    cudaGetSymbolAddress((void**)&pwfc2, g_wfc2);
    pfc1w = (float*)fc1_w; pfc2w = (float*)fc2_w;

    const int M = Bb * Ss;  // 4096

    // pack weights
    k_pack_qkv<<<((Ee / 2) * 1536 + 255) / 256, 256>>>(q_w, k_w, v_w, q_b, k_b, v_b);
    k_pack_w<<<((Ee / 2) * HIDh + 255) / 256, 256>>>(pfc1w, pwfc1, Ee / 2, HIDh);
    k_pack_w<<<((HIDh / 2) * Ee + 255) / 256, 256>>>(pfc2w, pwfc2, HIDh / 2, Ee);

    // embed (fp32 + packed)
    k_embed<<<(Bb * Ss * (Ee / 2) + 255) / 256, 256>>>(inputs, emb);

    float *px, *pattn;
    uint2 *pxp;
    cudaGetSymbolAddress((void**)&px, g_x);
    cudaGetSymbolAddress((void**)&pattn, g_attn);
    cudaGetSymbolAddress((void**)&pxp, g_xp);

    for (int l = 0; l < Ll; l++) {
        // fused QKV
        dim3 gq(1536 / 64, M / 128);
        k_qkv<<<gq, 256>>>();

        // window-summed V (packed)
        k_build_vs<<<(Bb * Hh * (SKk / 2) * DHh + 255) / 256, 256>>>();

        // gram
        dim3 gg(SP / 64, Ss / 128, Bb * Hh);
        k_gram<<<gg, 256>>>();

        // fused softmax + AV
        dim3 gf(Ss / 128, Bb * Hh);
        k_fsav<<<gf, 256, FSAV_SMEM>>>();

        // x = ln(attn)
        k_ln<<<M, 256>>>(pattn, ln_w, ln_b, px, pxp);

        // FFN
        dim3 g1(HIDh / 64, M / 128);
        k_fc1<<<g1, 256>>>(fc1_b);
        dim3 g2(Ee / 64, M / 128);
        k_fc2<<<g2, 256>>>(fc2_b);

        // x = ln(y)
        k_ln<<<M, 256>>>(pattn, ln_w, ln_b, px, pxp);
    }

    dim3 go(CHUNKS, Bb);
    k_out_partial<<<go, 256>>>(out_w);
    k_out_final<<<Bb, 32>>>(out_b, out);
}

// round 5
// speedup vs baseline: 4.1710x; 1.0060x over previous
#include <cuda_runtime.h>
#include <cuda_bf16.h>
#include <math.h>
#include <stdint.h>

#define Bb 2
#define Ss 2048
#define Ee 512
#define Hh 8
#define DHh 64
#define Ww 5
#define PADp 2
#define SKk 2044
#define HIDh 2048
#define Ll 6
#define OUTo 6
#define SCALEc 0.125f
#define CHUNKS 128
#define SP 2048

#define AST 132   // smem A row stride in uint2 (GEMM + P tiles)
#define BST 68    // smem B row stride in uint2
#define QST 148   // fattn Q tile row stride (uint2), per-dpair
#define KST 68    // fattn K tile row stride (uint2)
#define GS2 129   // fattn G tile row stride (floats, odd -> conflict-free shifted reads)

// ---------------- scratch ----------------
__device__ float g_x[Bb * Ss * Ee];                      // fp32 activations (LN out)
__device__ uint2 g_xp[Bb * Ss * (Ee / 2)];               // packed activations
__device__ float g_qkv[Bb * Ss * 1536];                  // fp32 qkv
__device__ uint2 g_qkvp[Bb * Ss * 768];                  // packed qkv (pairs along n == head dim)
__device__ uint2 g_hidp[(size_t)Bb * Ss * (HIDh / 2)];   // packed fc1 out
__device__ uint2 g_vsp[(size_t)Bb * Hh * (SP / 2) * DHh];// packed window-summed V (zeros beyond SKk)
__device__ float g_attn[Bb * Ss * Ee];
__device__ float g_part[Bb * CHUNKS * OUTo];
// packed weights
__device__ uint2 g_wqkv[(Ee / 2) * 1536];
__device__ float g_bqkv[1536];
__device__ uint2 g_wfc1[(Ee / 2) * HIDh];
__device__ uint2 g_wfc2[(HIDh / 2) * Ee];

// ---------------- bf16 split/pack ----------------
__device__ __forceinline__ uint2 sp2(float x, float y) {
    __nv_bfloat16 xh = __float2bfloat16_rn(x);
    __nv_bfloat16 yh = __float2bfloat16_rn(y);
    float xr = x - __bfloat162float(xh);
    float yr = y - __bfloat162float(yh);
    __nv_bfloat16 xl = __float2bfloat16_rn(xr);
    __nv_bfloat16 yl = __float2bfloat16_rn(yr);
    uint2 w;
    w.x = ((uint32_t)__bfloat16_as_ushort(yh) << 16) | (uint32_t)__bfloat16_as_ushort(xh);
    w.y = ((uint32_t)__bfloat16_as_ushort(yl) << 16) | (uint32_t)__bfloat16_as_ushort(xl);
    return w;
}

__device__ __forceinline__ void mma16(float c[4], uint32_t a0, uint32_t a1, uint32_t a2,
                                      uint32_t a3, uint32_t b0, uint32_t b1) {
    asm volatile(
        "mma.sync.aligned.m16n8k16.row.col.f32.bf16.bf16.f32 "
        "{%0,%1,%2,%3},{%4,%5,%6,%7},{%8,%9},{%0,%1,%2,%3};"
        : "+f"(c[0]), "+f"(c[1]), "+f"(c[2]), "+f"(c[3])
        : "r"(a0), "r"(a1), "r"(a2), "r"(a3), "r"(b0), "r"(b1));
}

// one 16-k chunk of bf16x3 mma over 128x64 tile (warp tile 32x32, 8 warps 4x2)
__device__ __forceinline__ void mma_chunk(const uint2* sA, const uint2* sB,
                                          int wm, int wn, int lane, float acc[2][4][4]) {
    int g = lane >> 2, tg = lane & 3;
    uint32_t ah[2][4], al[2][4];
#pragma unroll
    for (int mi = 0; mi < 2; mi++) {
        int m = wm * 32 + mi * 16 + g;
        uint2 u0 = sA[(size_t)tg * AST + m];
        uint2 u1 = sA[(size_t)tg * AST + m + 8];
        uint2 u2 = sA[(size_t)(tg + 4) * AST + m];
        uint2 u3 = sA[(size_t)(tg + 4) * AST + m + 8];
        ah[mi][0] = u0.x; al[mi][0] = u0.y;
        ah[mi][1] = u1.x; al[mi][1] = u1.y;
        ah[mi][2] = u2.x; al[mi][2] = u2.y;
        ah[mi][3] = u3.x; al[mi][3] = u3.y;
    }
#pragma unroll
    for (int ni = 0; ni < 4; ni++) {
        int n = wn * 32 + ni * 8 + g;
        uint2 v0 = sB[(size_t)tg * BST + n];
        uint2 v1 = sB[(size_t)(tg + 4) * BST + n];
#pragma unroll
        for (int mi = 0; mi < 2; mi++) {
            mma16(acc[mi][ni], ah[mi][0], ah[mi][1], ah[mi][2], ah[mi][3], v0.x, v1.x);
            mma16(acc[mi][ni], ah[mi][0], ah[mi][1], ah[mi][2], ah[mi][3], v0.y, v1.y);
            mma16(acc[mi][ni], al[mi][0], al[mi][1], al[mi][2], al[mi][3], v0.x, v1.x);
        }
    }
}

// ---------------- unified packed GEMM core ------------------------------------------
template <int BT, int BIAS, int RELU, int RES, int SCL, int WF32, int WPK>
__device__ __forceinline__ void gemm_core_p(
    const uint2* __restrict__ A, const uint2* __restrict__ B,
    const float* __restrict__ bias, const float* __restrict__ res,
    float* __restrict__ C, uint2* __restrict__ Cp,
    int K, int lda2, int ldb2, int ldc, int bm, int bn) {
    __shared__ uint2 sA[2][8 * AST];
    __shared__ uint2 sB[2][8 * BST];
    int t = threadIdx.x, lane = t & 31, wid = t >> 5;
    int wm = wid & 3, wn = wid >> 2;
    float acc[2][4][4] = {};

    int mA = t & 127, koA2 = (t >> 7) * 4;
    const uint2* Arow = A + (size_t)(bm + mA) * lda2 + koA2;

    int kpB = t >> 5, nB = (t & 31) * 2;
    int nBT = t & 63, kqBT = (t >> 6) * 2;
    const uint2* Bp = (BT == 0) ? (B + (size_t)kpB * ldb2 + bn + nB)
                                : (B + (size_t)(bn + nBT) * ldb2 + kqBT);

    uint4 a0 = *(const uint4*)(Arow);
    uint4 a1 = *(const uint4*)(Arow + 2);
    uint4 b0 = *(const uint4*)(Bp);

    {
        uint2* pa = sA[0];
        pa[(size_t)(koA2 + 0) * AST + mA] = make_uint2(a0.x, a0.y);
        pa[(size_t)(koA2 + 1) * AST + mA] = make_uint2(a0.z, a0.w);
        pa[(size_t)(koA2 + 2) * AST + mA] = make_uint2(a1.x, a1.y);
        pa[(size_t)(koA2 + 3) * AST + mA] = make_uint2(a1.z, a1.w);
        uint2* pb = sB[0];
        if (BT == 0) {
            pb[(size_t)kpB * BST + nB]     = make_uint2(b0.x, b0.y);
            pb[(size_t)kpB * BST + nB + 1] = make_uint2(b0.z, b0.w);
        } else {
            pb[(size_t)(kqBT + 0) * BST + nBT] = make_uint2(b0.x, b0.y);
            pb[(size_t)(kqBT + 1) * BST + nBT] = make_uint2(b0.z, b0.w);
        }
    }
    __syncthreads();

    int nch = K >> 4;
    for (int ch = 0; ch < nch; ch++) {
        int s = ch & 1;
        bool more = (ch + 1 < nch);
        if (more) {
            int off = (ch + 1) * 8;
            a0 = *(const uint4*)(Arow + off);
            a1 = *(const uint4*)(Arow + off + 2);
            const uint2* Bn = (BT == 0) ? (Bp + (size_t)(ch + 1) * 8 * ldb2) : (Bp + off);
            b0 = *(const uint4*)(Bn);
        }
        mma_chunk(sA[s], sB[s], wm, wn, lane, acc);
        if (more) {
            int s2 = s ^ 1;
            uint2* pa = sA[s2];
            pa[(size_t)(koA2 + 0) * AST + mA] = make_uint2(a0.x, a0.y);
            pa[(size_t)(koA2 + 1) * AST + mA] = make_uint2(a0.z, a0.w);
            pa[(size_t)(koA2 + 2) * AST + mA] = make_uint2(a1.x, a1.y);
            pa[(size_t)(koA2 + 3) * AST + mA] = make_uint2(a1.z, a1.w);
            uint2* pb = sB[s2];
            if (BT == 0) {
                pb[(size_t)kpB * BST + nB]     = make_uint2(b0.x, b0.y);
                pb[(size_t)kpB * BST + nB + 1] = make_uint2(b0.z, b0.w);
            } else {
                pb[(size_t)(kqBT + 0) * BST + nBT] = make_uint2(b0.x, b0.y);
                pb[(size_t)(kqBT + 1) * BST + nBT] = make_uint2(b0.z, b0.w);
            }
        }
        __syncthreads();
    }

    int g = lane >> 2, tg = lane & 3;
#pragma unroll
    for (int mi = 0; mi < 2; mi++)
#pragma unroll
        for (int ni = 0; ni < 4; ni++) {
            int r0 = bm + wm * 32 + mi * 16 + g;
            int c0 = bn + wn * 32 + ni * 8 + 2 * tg;
            float v00 = acc[mi][ni][0], v01 = acc[mi][ni][1];
            float v10 = acc[mi][ni][2], v11 = acc[mi][ni][3];
            if (SCL) { v00 *= SCALEc; v01 *= SCALEc; v10 *= SCALEc; v11 *= SCALEc; }
            if (BIAS) {
                float bv0 = bias[c0], bv1 = bias[c0 + 1];
                v00 += bv0; v01 += bv1; v10 += bv0; v11 += bv1;
            }
            if (RES) {
                v00 += res[(size_t)r0 * ldc + c0];
                v01 += res[(size_t)r0 * ldc + c0 + 1];
                v10 += res[(size_t)(r0 + 8) * ldc + c0];
                v11 += res[(size_t)(r0 + 8) * ldc + c0 + 1];
            }
            if (RELU) {
                v00 = fmaxf(v00, 0.f); v01 = fmaxf(v01, 0.f);
                v10 = fmaxf(v10, 0.f); v11 = fmaxf(v11, 0.f);
            }
            if (WF32) {
                C[(size_t)r0 * ldc + c0] = v00;
                C[(size_t)r0 * ldc + c0 + 1] = v01;
                C[(size_t)(r0 + 8) * ldc + c0] = v10;
                C[(size_t)(r0 + 8) * ldc + c0 + 1] = v11;
            }
            if (WPK) {
                Cp[(size_t)r0 * (ldc >> 1) + (c0 >> 1)] = sp2(v00, v01);
                Cp[(size_t)(r0 + 8) * (ldc >> 1) + (c0 >> 1)] = sp2(v10, v11);
            }
        }
}

// ---------------- GEMM kernel wrappers ----------------
__launch_bounds__(256)
__global__ void k_qkv() {
    gemm_core_p<0, 1, 0, 0, 0, 1, 1>(g_xp, g_wqkv, g_bqkv, nullptr, g_qkv, g_qkvp,
                                     Ee, Ee / 2, 1536, 1536,
                                     blockIdx.y * 128, blockIdx.x * 64);
}

__launch_bounds__(256)
__global__ void k_fc1(const float* __restrict__ bias) {
    gemm_core_p<0, 1, 1, 0, 0, 0, 1>(g_xp, g_wfc1, bias, nullptr, nullptr, g_hidp,
                                     Ee, Ee / 2, HIDh, HIDh,
                                     blockIdx.y * 128, blockIdx.x * 64);
}

__launch_bounds__(256)
__global__ void k_fc2(const float* __restrict__ bias) {
    gemm_core_p<0, 1, 0, 1, 0, 1, 0>(g_hidp, g_wfc2, bias, g_x, g_attn, nullptr,
                                     HIDh, HIDh / 2, Ee, Ee,
                                     blockIdx.y * 128, blockIdx.x * 64);
}

// ---------------- weight packing (once per call) ----------------
__global__ void k_pack_qkv(const float* __restrict__ qw, const float* __restrict__ kw,
                           const float* __restrict__ vw, const float* __restrict__ qb,
                           const float* __restrict__ kb, const float* __restrict__ vb) {
    int idx = blockIdx.x * 256 + threadIdx.x;
    if (idx < (Ee / 2) * 1536) {
        int n = idx % 1536, kp = idx / 1536;
        const float* W = (n < 512) ? qw : (n < 1024 ? kw : vw);
        int c = n & 511;
        g_wqkv[idx] = sp2(W[(size_t)(2 * kp) * 512 + c], W[(size_t)(2 * kp + 1) * 512 + c]);
    }
    if (idx < 1536)
        g_bqkv[idx] = (idx < 512) ? qb[idx] : (idx < 1024 ? kb[idx - 512] : vb[idx - 1024]);
}

__global__ void k_pack_w(const float* __restrict__ W, uint2* __restrict__ out, int Kp, int N) {
    int idx = blockIdx.x * 256 + threadIdx.x;
    if (idx >= Kp * N) return;
    int n = idx % N, kp = idx / N;
    out[idx] = sp2(W[(size_t)(2 * kp) * N + n], W[(size_t)(2 * kp + 1) * N + n]);
}

// ---------------- embedding + positional encoding ----------------
__global__ void k_embed(const int* __restrict__ inp, const float* __restrict__ emb) {
    int idx = blockIdx.x * blockDim.x + threadIdx.x;
    if (idx >= Bb * Ss * (Ee / 2)) return;
    int ep = idx % (Ee / 2);
    int bs = idx / (Ee / 2);
    int s = bs % Ss;
    int tok = inp[bs];
    int e0 = 2 * ep;
    const float LN1E4 = 9.210340371976184f;
    float freq = expf(-(float)e0 * (LN1E4 / (float)Ee));
    float ang = (float)s * freq;
    float x0 = emb[(size_t)tok * Ee + e0] + sinf(ang);
    float x1 = emb[(size_t)tok * Ee + e0 + 1] + cosf(ang);
    g_x[(size_t)bs * Ee + e0] = x0;
    g_x[(size_t)bs * Ee + e0 + 1] = x1;
    g_xp[(size_t)bs * (Ee / 2) + ep] = sp2(x0, x1);
}

// ---------------- window-summed V, packed pairs along k-rows ----------------
__global__ void k_build_vs() {
    int idx = blockIdx.x * blockDim.x + threadIdx.x;
    if (idx >= Bb * Hh * (SKk / 2) * DHh) return;
    int d = idx & 63;
    int rest = idx >> 6;
    int kp = rest % (SKk / 2);
    int bh = rest / (SKk / 2);
    int b = bh >> 3, h = bh & 7;
    const float* Vp = g_qkv + (size_t)b * Ss * 1536 + 1024 + h * DHh + d;
    int k = 2 * kp;
    float v0 = Vp[(size_t)(k + 0) * 1536];
    float v1 = Vp[(size_t)(k + 1) * 1536];
    float v2 = Vp[(size_t)(k + 2) * 1536];
    float v3 = Vp[(size_t)(k + 3) * 1536];
    float v4 = Vp[(size_t)(k + 4) * 1536];
    float v5 = Vp[(size_t)(k + 5) * 1536];
    float s0 = v0 + v1 + v2 + v3 + v4;
    float s1 = v1 + v2 + v3 + v4 + v5;
    g_vsp[((size_t)bh * (SP / 2) + kp) * DHh + d] = sp2(s0, s1);
}

// ---------------- fused attention: gram-in-smem + flash softmax + AV ----------------
// smem layout (bytes):
#define FA_OFF_Q  0
#define FA_OFF_K  37888                        // 32*148*8
#define FA_OFF_G  (FA_OFF_K + 17408)           // 32*68*8
#define FA_OFF_P  (FA_OFF_G + 68112)           // 132*129*4
#define FA_OFF_V  (FA_OFF_P + 33792)           // 32*132*8
#define FA_OFF_M  (FA_OFF_V + 17408)           // 32*68*8
#define FA_SMEM   (FA_OFF_M + 896 * 4)

__launch_bounds__(256)
__global__ void k_fattn() {
    extern __shared__ char dyn[];
    uint2* sQ = (uint2*)(dyn + FA_OFF_Q);   // [32 dpair][QST rows]
    uint2* sK = (uint2*)(dyn + FA_OFF_K);   // [32 dpair][KST cols]
    float* sG = (float*)(dyn + FA_OFF_G);   // [132 rows][GS2], ring cols (c & 127)
    uint2* sP = (uint2*)(dyn + FA_OFF_P);   // [32 kpair][AST rows]
    uint2* sV = (uint2*)(dyn + FA_OFF_V);   // [32 kpair][BST cols]
    float* sM = (float*)(dyn + FA_OFF_M);
    float* sL = sM + 128;
    float* sFac = sM + 256;
    float* sRedM = sM + 384;   // [2][128]
    float* sRedS = sM + 640;   // [2][128]

    int qt = blockIdx.x;
    int bh = blockIdx.y;
    int b = bh >> 3, h = bh & 7;
    int q0 = qt * 128;
    const uint2* Qb = g_qkvp + (size_t)b * Ss * 768 + h * 32;
    const uint2* Kb = g_qkvp + (size_t)b * Ss * 768 + 256 + h * 32;
    const uint2* Vb = g_vsp + (size_t)bh * (SP / 2) * DHh;

    int t = threadIdx.x, lane = t & 31, wid = t >> 5;
    int wm = wid & 3, wn = wid >> 2;
    int g = lane >> 2, tg = lane & 3;
    float acc[2][4][4] = {};

    if (t < 128) { sM[t] = -1e30f; sL[t] = 0.f; }

    int srow = t & 127, kh = t >> 7;

    // ---- load Q tile (144 rows padded, rows map to global q0-2+r) ----
    {
        int dpq = (t & 3) * 8;
        int rr = t >> 2;
#pragma unroll
        for (int rb = 0; rb < 144; rb += 64) {
            int r = rb + rr;
            if (r < 144) {
                int gr = q0 - 2 + r;
                bool ok = (r < 132) && (gr >= 0) && (gr < Ss);
#pragma unroll
                for (int u = 0; u < 8; u += 2) {
                    uint4 v = make_uint4(0, 0, 0, 0);
                    if (ok) v = *(const uint4*)(Qb + (size_t)gr * 768 + dpq + u);
                    sQ[(size_t)(dpq + u) * QST + r] = make_uint2(v.x, v.y);
                    sQ[(size_t)(dpq + u + 1) * QST + r] = make_uint2(v.z, v.w);
                }
            }
        }
    }

    // ---- load K panel 0 ----
    {
        int r = t >> 2, dpq = (t & 3) * 8;
        const uint2* src = Kb + (size_t)r * 768 + dpq;
#pragma unroll
        for (int u = 0; u < 8; u += 2) {
            uint4 v = *(const uint4*)(src + u);
            sK[(size_t)(dpq + u) * KST + r] = make_uint2(v.x, v.y);
            sK[(size_t)(dpq + u + 1) * KST + r] = make_uint2(v.z, v.w);
        }
    }
    __syncthreads();

    // ---- compute G panel 0 into ring slot 0 ----
    {
        float accg[9][4] = {};
#pragma unroll
        for (int c = 0; c < 4; c++) {
            int nb = wid * 8 + g;
            uint2 v0 = sK[(size_t)(c * 8 + tg) * KST + nb];
            uint2 v1 = sK[(size_t)(c * 8 + tg + 4) * KST + nb];
#pragma unroll
            for (int mi = 0; mi < 9; mi++) {
                int m = mi * 16 + g;
                uint2 u0 = sQ[(size_t)(c * 8 + tg) * QST + m];
                uint2 u1 = sQ[(size_t)(c * 8 + tg) * QST + m + 8];
                uint2 u2 = sQ[(size_t)(c * 8 + tg + 4) * QST + m];
                uint2 u3 = sQ[(size_t)(c * 8 + tg + 4) * QST + m + 8];
                mma16(accg[mi], u0.x, u1.x, u2.x, u3.x, v0.x, v1.x);
                mma16(accg[mi], u0.x, u1.x, u2.x, u3.x, v0.y, v1.y);
                mma16(accg[mi], u0.y, u1.y, u2.y, u3.y, v0.x, v1.x);
            }
        }
        int c0 = wid * 8 + 2 * tg;
#pragma unroll
        for (int mi = 0; mi < 9; mi++) {
            int r0 = mi * 16 + g;
            if (r0 < 132) {
                sG[r0 * GS2 + c0] = accg[mi][0] * SCALEc;
                sG[r0 * GS2 + c0 + 1] = accg[mi][1] * SCALEc;
            }
            if (r0 + 8 < 132) {
                sG[(r0 + 8) * GS2 + c0] = accg[mi][2] * SCALEc;
                sG[(r0 + 8) * GS2 + c0 + 1] = accg[mi][3] * SCALEc;
            }
        }
    }
    __syncthreads();

    // ---- k sweep ----
    for (int it = 0; it < 32; it++) {
        int k0 = it * 64;
        bool more = (it < 31);

        // load K panel it+1
        if (more) {
            int r = t >> 2, dpq = (t & 3) * 8;
            const uint2* src = Kb + (size_t)((it + 1) * 64 + r) * 768 + dpq;
#pragma unroll
            for (int u = 0; u < 8; u += 2) {
                uint4 v = *(const uint4*)(src + u);
                sK[(size_t)(dpq + u) * KST + r] = make_uint2(v.x, v.y);
                sK[(size_t)(dpq + u + 1) * KST + r] = make_uint2(v.z, v.w);
            }
        }
        // load V tile it
        {
            int kpB = t >> 5, dB = (t & 31) * 2;
#pragma unroll
            for (int r = 0; r < 4; r++) {
                int kp = r * 8 + kpB;
                uint4 v = *(const uint4*)(Vb + (size_t)((k0 >> 1) + kp) * DHh + dB);
                sV[(size_t)kp * BST + dB] = make_uint2(v.x, v.y);
                sV[(size_t)kp * BST + dB + 1] = make_uint2(v.z, v.w);
            }
        }
        __syncthreads();   // A: sK/sV visible

        // compute G panel it+1 into ring slot (it+1)&1
        if (more) {
            float accg[9][4] = {};
#pragma unroll
            for (int c = 0; c < 4; c++) {
                int nb = wid * 8 + g;
                uint2 v0 = sK[(size_t)(c * 8 + tg) * KST + nb];
                uint2 v1 = sK[(size_t)(c * 8 + tg + 4) * KST + nb];
#pragma unroll
                for (int mi = 0; mi < 9; mi++) {
                    int m = mi * 16 + g;
                    uint2 u0 = sQ[(size_t)(c * 8 + tg) * QST + m];
                    uint2 u1 = sQ[(size_t)(c * 8 + tg) * QST + m + 8];
                    uint2 u2 = sQ[(size_t)(c * 8 + tg + 4) * QST + m];
                    uint2 u3 = sQ[(size_t)(c * 8 + tg + 4) * QST + m + 8];
                    mma16(accg[mi], u0.x, u1.x, u2.x, u3.x, v0.x, v1.x);
                    mma16(accg[mi], u0.x, u1.x, u2.x, u3.x, v0.y, v1.y);
                    mma16(accg[mi], u0.y, u1.y, u2.y, u3.y, v0.x, v1.x);
                }
            }
            int ringb = ((it + 1) & 1) * 64;
            int c0 = ringb + wid * 8 + 2 * tg;
#pragma unroll
            for (int mi = 0; mi < 9; mi++) {
                int r0 = mi * 16 + g;
                if (r0 < 132) {
                    sG[r0 * GS2 + c0] = accg[mi][0] * SCALEc;
                    sG[r0 * GS2 + c0 + 1] = accg[mi][1] * SCALEc;
                }
                if (r0 + 8 < 132) {
                    sG[(r0 + 8) * GS2 + c0] = accg[mi][2] * SCALEc;
                    sG[(r0 + 8) * GS2 + c0 + 1] = accg[mi][3] * SCALEc;
                }
            }
        }
        __syncthreads();   // B: sG visible

        // scores: thread handles row srow, 32 consecutive k starting at kh*32
        float sv[32];
        float lmax = -1e30f;
        int kbase = kh * 32;
#pragma unroll
        for (int i = 0; i < 32; i++) {
            int kg = k0 + kbase + i;
            float s = -1e30f;
            if (kg < SKk) {
                s = 0.f;
#pragma unroll
                for (int j = 0; j < Ww; j++)
                    s += sG[(srow + j) * GS2 + ((kg + j) & 127)];
            }
            sv[i] = s;
            lmax = fmaxf(lmax, s);
        }
        sRedM[kh * 128 + srow] = lmax;
        __syncthreads();   // C

        float mold = sM[srow];
        float mnew = fmaxf(mold, fmaxf(sRedM[srow], sRedM[128 + srow]));
        float lsum = 0.f;
#pragma unroll
        for (int i = 0; i < 32; i += 2) {
            float p0 = __expf(sv[i] - mnew);
            float p1 = __expf(sv[i + 1] - mnew);
            lsum += p0 + p1;
            sP[(size_t)(kh * 16 + (i >> 1)) * AST + srow] = sp2(p0, p1);
        }
        sRedS[kh * 128 + srow] = lsum;
        __syncthreads();   // D

        if (kh == 0) {
            float fac = __expf(mold - mnew);
            sL[srow] = sL[srow] * fac + sRedS[srow] + sRedS[128 + srow];
            sM[srow] = mnew;
            sFac[srow] = fac;
        }
        __syncthreads();   // E

        // rescale + AV MMA
        {
            float f0 = sFac[wm * 32 + g];
            float f1 = sFac[wm * 32 + g + 8];
            float f2 = sFac[wm * 32 + g + 16];
            float f3 = sFac[wm * 32 + g + 24];
#pragma unroll
            for (int ni = 0; ni < 4; ni++) {
                acc[0][ni][0] *= f0; acc[0][ni][1] *= f0;
                acc[0][ni][2] *= f1; acc[0][ni][3] *= f1;
                acc[1][ni][0] *= f2; acc[1][ni][1] *= f2;
                acc[1][ni][2] *= f3; acc[1][ni][3] *= f3;
            }
#pragma unroll
            for (int c = 0; c < 4; c++)
                mma_chunk(sP + (size_t)c * 8 * AST, sV + (size_t)c * 8 * BST, wm, wn, lane, acc);
        }
        __syncthreads();   // F: protect sP/sV/sK/sG for next iteration
    }

    float inv0 = 1.f / sL[wm * 32 + g];
    float inv1 = 1.f / sL[wm * 32 + g + 8];
    float inv2 = 1.f / sL[wm * 32 + g + 16];
    float inv3 = 1.f / sL[wm * 32 + g + 24];
    float* Cb = g_attn + (size_t)b * Ss * Ee + h * DHh;
#pragma unroll
    for (int mi = 0; mi < 2; mi++)
#pragma unroll
        for (int ni = 0; ni < 4; ni++) {
            int r0 = q0 + wm * 32 + mi * 16 + g;
            int c0 = wn * 32 + ni * 8 + 2 * tg;
            float i0 = mi ? inv2 : inv0;
            float i1 = mi ? inv3 : inv1;
            Cb[(size_t)r0 * Ee + c0] = acc[mi][ni][0] * i0;
            Cb[(size_t)r0 * Ee + c0 + 1] = acc[mi][ni][1] * i0;
            Cb[(size_t)(r0 + 8) * Ee + c0] = acc[mi][ni][2] * i1;
            Cb[(size_t)(r0 + 8) * Ee + c0 + 1] = acc[mi][ni][3] * i1;
        }
}

// ---------------- LayerNorm (fp32 + packed out) ----------------
__launch_bounds__(256)
__global__ void k_ln(const float* __restrict__ in, const float* __restrict__ w,
                     const float* __restrict__ bz, float* __restrict__ out,
                     uint2* __restrict__ outp) {
    int row = blockIdx.x;
    const float* x = in + (size_t)row * Ee;
    __shared__ float red[256];
    int t = threadIdx.x;
    float x0 = x[2 * t], x1 = x[2 * t + 1];
    red[t] = x0 + x1; __syncthreads();
    for (int off = 128; off > 0; off >>= 1) {
        if (t < off) red[t] += red[t + off];
        __syncthreads();
    }
    float m = red[0] * (1.0f / Ee);
    __syncthreads();
    float d0 = x0 - m, d1 = x1 - m;
    red[t] = d0 * d0 + d1 * d1; __syncthreads();
    for (int off = 128; off > 0; off >>= 1) {
        if (t < off) red[t] += red[t + off];
        __syncthreads();
    }
    float inv = rsqrtf(red[0] * (1.0f / Ee) + 1e-5f);
    float y0 = d0 * inv * w[2 * t] + bz[2 * t];
    float y1 = d1 * inv * w[2 * t + 1] + bz[2 * t + 1];
    out[(size_t)row * Ee + 2 * t] = y0;
    out[(size_t)row * Ee + 2 * t + 1] = y1;
    outp[(size_t)row * (Ee / 2) + t] = sp2(y0, y1);
}

// ---------------- output head ----------------
__launch_bounds__(256)
__global__ void k_out_partial(const float* __restrict__ ow) {
    int b = blockIdx.y, c = blockIdx.x;
    const int per = (Ss * Ee) / CHUNKS;
    const float* x = g_x + (size_t)b * Ss * Ee + (size_t)c * per;
    const float* wr = ow + (size_t)c * per * OUTo;
    int t = threadIdx.x;
    float acc[OUTo] = {};
    for (int i = t; i < per; i += 256) {
        float xv = x[i];
#pragma unroll
        for (int o = 0; o < OUTo; o++) acc[o] = fmaf(xv, wr[(size_t)i * OUTo + o], acc[o]);
    }
    __shared__ float red[256 * OUTo];
#pragma unroll
    for (int o = 0; o < OUTo; o++) red[t * OUTo + o] = acc[o];
    __syncthreads();
    for (int off = 128; off > 0; off >>= 1) {
        if (t < off) {
#pragma unroll
            for (int o = 0; o < OUTo; o++)
                red[t * OUTo + o] += red[(t + off) * OUTo + o];
        }
        __syncthreads();
    }
    if (t == 0) {
#pragma unroll
        for (int o = 0; o < OUTo; o++)
            g_part[((size_t)b * CHUNKS + c) * OUTo + o] = red[o];
    }
}

__global__ void k_out_final(const float* __restrict__ ob, float* __restrict__ out) {
    int b = blockIdx.x;
    int o = threadIdx.x;
    if (o < OUTo) {
        float s = ob[o];
        for (int c = 0; c < CHUNKS; c++) s += g_part[(b * CHUNKS + c) * OUTo + o];
        out[b * OUTo + o] = s;
    }
}

// ---------------- host launcher ----------------
extern "C" void kernel_launch(void* const* d_in, const int* in_sizes, int n_in,
                              void* d_out, int out_size) {
    const int*   inputs = (const int*)d_in[0];
    const float* emb    = (const float*)d_in[1];
    const float* ln_w   = (const float*)d_in[2];
    const float* ln_b   = (const float*)d_in[3];
    const float* q_w    = (const float*)d_in[4];
    const float* q_b    = (const float*)d_in[5];
    const float* k_w    = (const float*)d_in[6];
    const float* k_b    = (const float*)d_in[7];
    const float* v_w    = (const float*)d_in[8];
    const float* v_b    = (const float*)d_in[9];
    const float* fc1_w  = (const float*)d_in[10];
    const float* fc1_b  = (const float*)d_in[11];
    const float* fc2_w  = (const float*)d_in[12];
    const float* fc2_b  = (const float*)d_in[13];
    const float* out_w  = (const float*)d_in[14];
    const float* out_b  = (const float*)d_in[15];
    float* out = (float*)d_out;

    static int smem_set = 0;
    if (!smem_set) {
        cudaFuncSetAttribute(k_fattn, cudaFuncAttributeMaxDynamicSharedMemorySize, FA_SMEM);
        smem_set = 1;
    }

    uint2 *pwfc1, *pwfc2;
    cudaGetSymbolAddress((void**)&pwfc1, g_wfc1);
    cudaGetSymbolAddress((void**)&pwfc2, g_wfc2);

    const int M = Bb * Ss;  // 4096

    // pack weights
    k_pack_qkv<<<((Ee / 2) * 1536 + 255) / 256, 256>>>(q_w, k_w, v_w, q_b, k_b, v_b);
    k_pack_w<<<((Ee / 2) * HIDh + 255) / 256, 256>>>(fc1_w, pwfc1, Ee / 2, HIDh);
    k_pack_w<<<((HIDh / 2) * Ee + 255) / 256, 256>>>(fc2_w, pwfc2, HIDh / 2, Ee);

    // embed (fp32 + packed)
    k_embed<<<(Bb * Ss * (Ee / 2) + 255) / 256, 256>>>(inputs, emb);

    float *px, *pattn;
    uint2 *pxp;
    cudaGetSymbolAddress((void**)&px, g_x);
    cudaGetSymbolAddress((void**)&pattn, g_attn);
    cudaGetSymbolAddress((void**)&pxp, g_xp);

    for (int l = 0; l < Ll; l++) {
        // fused QKV
        dim3 gq(1536 / 64, M / 128);
        k_qkv<<<gq, 256>>>();

        // window-summed V (packed)
        k_build_vs<<<(Bb * Hh * (SKk / 2) * DHh + 255) / 256, 256>>>();

        // fused gram + softmax + AV
        dim3 gf(Ss / 128, Bb * Hh);
        k_fattn<<<gf, 256, FA_SMEM>>>();

        // x = ln(attn)
        k_ln<<<M, 256>>>(pattn, ln_w, ln_b, px, pxp);

        // FFN
        dim3 g1(HIDh / 64, M / 128);
        k_fc1<<<g1, 256>>>(fc1_b);
        dim3 g2(Ee / 64, M / 128);
        k_fc2<<<g2, 256>>>(fc2_b);

        // x = ln(y)
        k_ln<<<M, 256>>>(pattn, ln_w, ln_b, px, pxp);
    }

    dim3 go(CHUNKS, Bb);
    k_out_partial<<<go, 256>>>(out_w);
    k_out_final<<<Bb, 32>>>(out_b, out);
}

// round 6
// speedup vs baseline: 4.1726x; 1.0004x over previous
#include <cuda_runtime.h>
#include <cuda_bf16.h>
#include <math.h>
#include <stdint.h>

#define Bb 2
#define Ss 2048
#define Ee 512
#define Hh 8
#define DHh 64
#define Ww 5
#define PADp 2
#define SKk 2044
#define HIDh 2048
#define Ll 6
#define OUTo 6
#define SCALEc 0.125f
#define CHUNKS 128
#define SP 2048

#define AST 132   // GEMM smem A row stride (uint2)
#define BST 68    // GEMM smem B row stride (uint2)
// fattn strides
#define QST2 84   // Q tile row stride (uint2), 80 rows used
#define KST 68
#define PST 68
#define VST 68
#define GS2 129   // G ring row stride (floats), 128 ring cols

// ---------------- scratch ----------------
__device__ float g_x[Bb * Ss * Ee];
__device__ uint2 g_xp[Bb * Ss * (Ee / 2)];
__device__ float g_qkv[Bb * Ss * 1536];
__device__ uint2 g_qkvp[Bb * Ss * 768];
__device__ uint2 g_hidp[(size_t)Bb * Ss * (HIDh / 2)];
__device__ uint2 g_vsp[(size_t)Bb * Hh * (SP / 2) * DHh];
__device__ float g_attn[Bb * Ss * Ee];
__device__ float g_part[Bb * CHUNKS * OUTo];
__device__ uint2 g_wqkv[(Ee / 2) * 1536];
__device__ float g_bqkv[1536];
__device__ uint2 g_wfc1[(Ee / 2) * HIDh];
__device__ uint2 g_wfc2[(HIDh / 2) * Ee];

// ---------------- bf16 split/pack ----------------
__device__ __forceinline__ uint2 sp2(float x, float y) {
    __nv_bfloat16 xh = __float2bfloat16_rn(x);
    __nv_bfloat16 yh = __float2bfloat16_rn(y);
    float xr = x - __bfloat162float(xh);
    float yr = y - __bfloat162float(yh);
    __nv_bfloat16 xl = __float2bfloat16_rn(xr);
    __nv_bfloat16 yl = __float2bfloat16_rn(yr);
    uint2 w;
    w.x = ((uint32_t)__bfloat16_as_ushort(yh) << 16) | (uint32_t)__bfloat16_as_ushort(xh);
    w.y = ((uint32_t)__bfloat16_as_ushort(yl) << 16) | (uint32_t)__bfloat16_as_ushort(xl);
    return w;
}

__device__ __forceinline__ void mma16(float c[4], uint32_t a0, uint32_t a1, uint32_t a2,
                                      uint32_t a3, uint32_t b0, uint32_t b1) {
    asm volatile(
        "mma.sync.aligned.m16n8k16.row.col.f32.bf16.bf16.f32 "
        "{%0,%1,%2,%3},{%4,%5,%6,%7},{%8,%9},{%0,%1,%2,%3};"
        : "+f"(c[0]), "+f"(c[1]), "+f"(c[2]), "+f"(c[3])
        : "r"(a0), "r"(a1), "r"(a2), "r"(a3), "r"(b0), "r"(b1));
}

// one 16-k chunk of bf16x3 mma over 128x64 tile (warp tile 32x32, 8 warps 4x2)
__device__ __forceinline__ void mma_chunk(const uint2* sA, const uint2* sB,
                                          int wm, int wn, int lane, float acc[2][4][4]) {
    int g = lane >> 2, tg = lane & 3;
    uint32_t ah[2][4], al[2][4];
#pragma unroll
    for (int mi = 0; mi < 2; mi++) {
        int m = wm * 32 + mi * 16 + g;
        uint2 u0 = sA[(size_t)tg * AST + m];
        uint2 u1 = sA[(size_t)tg * AST + m + 8];
        uint2 u2 = sA[(size_t)(tg + 4) * AST + m];
        uint2 u3 = sA[(size_t)(tg + 4) * AST + m + 8];
        ah[mi][0] = u0.x; al[mi][0] = u0.y;
        ah[mi][1] = u1.x; al[mi][1] = u1.y;
        ah[mi][2] = u2.x; al[mi][2] = u2.y;
        ah[mi][3] = u3.x; al[mi][3] = u3.y;
    }
#pragma unroll
    for (int ni = 0; ni < 4; ni++) {
        int n = wn * 32 + ni * 8 + g;
        uint2 v0 = sB[(size_t)tg * BST + n];
        uint2 v1 = sB[(size_t)(tg + 4) * BST + n];
#pragma unroll
        for (int mi = 0; mi < 2; mi++) {
            mma16(acc[mi][ni], ah[mi][0], ah[mi][1], ah[mi][2], ah[mi][3], v0.x, v1.x);
            mma16(acc[mi][ni], ah[mi][0], ah[mi][1], ah[mi][2], ah[mi][3], v0.y, v1.y);
            mma16(acc[mi][ni], al[mi][0], al[mi][1], al[mi][2], al[mi][3], v0.x, v1.x);
        }
    }
}

// ---------------- unified packed GEMM core ------------------------------------------
template <int BT, int BIAS, int RELU, int RES, int SCL, int WF32, int WPK>
__device__ __forceinline__ void gemm_core_p(
    const uint2* __restrict__ A, const uint2* __restrict__ B,
    const float* __restrict__ bias, const float* __restrict__ res,
    float* __restrict__ C, uint2* __restrict__ Cp,
    int K, int lda2, int ldb2, int ldc, int bm, int bn) {
    __shared__ uint2 sA[2][8 * AST];
    __shared__ uint2 sB[2][8 * BST];
    int t = threadIdx.x, lane = t & 31, wid = t >> 5;
    int wm = wid & 3, wn = wid >> 2;
    float acc[2][4][4] = {};

    int mA = t & 127, koA2 = (t >> 7) * 4;
    const uint2* Arow = A + (size_t)(bm + mA) * lda2 + koA2;

    int kpB = t >> 5, nB = (t & 31) * 2;
    int nBT = t & 63, kqBT = (t >> 6) * 2;
    const uint2* Bp = (BT == 0) ? (B + (size_t)kpB * ldb2 + bn + nB)
                                : (B + (size_t)(bn + nBT) * ldb2 + kqBT);

    uint4 a0 = *(const uint4*)(Arow);
    uint4 a1 = *(const uint4*)(Arow + 2);
    uint4 b0 = *(const uint4*)(Bp);

    {
        uint2* pa = sA[0];
        pa[(size_t)(koA2 + 0) * AST + mA] = make_uint2(a0.x, a0.y);
        pa[(size_t)(koA2 + 1) * AST + mA] = make_uint2(a0.z, a0.w);
        pa[(size_t)(koA2 + 2) * AST + mA] = make_uint2(a1.x, a1.y);
        pa[(size_t)(koA2 + 3) * AST + mA] = make_uint2(a1.z, a1.w);
        uint2* pb = sB[0];
        if (BT == 0) {
            pb[(size_t)kpB * BST + nB]     = make_uint2(b0.x, b0.y);
            pb[(size_t)kpB * BST + nB + 1] = make_uint2(b0.z, b0.w);
        } else {
            pb[(size_t)(kqBT + 0) * BST + nBT] = make_uint2(b0.x, b0.y);
            pb[(size_t)(kqBT + 1) * BST + nBT] = make_uint2(b0.z, b0.w);
        }
    }
    __syncthreads();

    int nch = K >> 4;
    for (int ch = 0; ch < nch; ch++) {
        int s = ch & 1;
        bool more = (ch + 1 < nch);
        if (more) {
            int off = (ch + 1) * 8;
            a0 = *(const uint4*)(Arow + off);
            a1 = *(const uint4*)(Arow + off + 2);
            const uint2* Bn = (BT == 0) ? (Bp + (size_t)(ch + 1) * 8 * ldb2) : (Bp + off);
            b0 = *(const uint4*)(Bn);
        }
        mma_chunk(sA[s], sB[s], wm, wn, lane, acc);
        if (more) {
            int s2 = s ^ 1;
            uint2* pa = sA[s2];
            pa[(size_t)(koA2 + 0) * AST + mA] = make_uint2(a0.x, a0.y);
            pa[(size_t)(koA2 + 1) * AST + mA] = make_uint2(a0.z, a0.w);
            pa[(size_t)(koA2 + 2) * AST + mA] = make_uint2(a1.x, a1.y);
            pa[(size_t)(koA2 + 3) * AST + mA] = make_uint2(a1.z, a1.w);
            uint2* pb = sB[s2];
            if (BT == 0) {
                pb[(size_t)kpB * BST + nB]     = make_uint2(b0.x, b0.y);
                pb[(size_t)kpB * BST + nB + 1] = make_uint2(b0.z, b0.w);
            } else {
                pb[(size_t)(kqBT + 0) * BST + nBT] = make_uint2(b0.x, b0.y);
                pb[(size_t)(kqBT + 1) * BST + nBT] = make_uint2(b0.z, b0.w);
            }
        }
        __syncthreads();
    }

    int g = lane >> 2, tg = lane & 3;
#pragma unroll
    for (int mi = 0; mi < 2; mi++)
#pragma unroll
        for (int ni = 0; ni < 4; ni++) {
            int r0 = bm + wm * 32 + mi * 16 + g;
            int c0 = bn + wn * 32 + ni * 8 + 2 * tg;
            float v00 = acc[mi][ni][0], v01 = acc[mi][ni][1];
            float v10 = acc[mi][ni][2], v11 = acc[mi][ni][3];
            if (SCL) { v00 *= SCALEc; v01 *= SCALEc; v10 *= SCALEc; v11 *= SCALEc; }
            if (BIAS) {
                float bv0 = bias[c0], bv1 = bias[c0 + 1];
                v00 += bv0; v01 += bv1; v10 += bv0; v11 += bv1;
            }
            if (RES) {
                v00 += res[(size_t)r0 * ldc + c0];
                v01 += res[(size_t)r0 * ldc + c0 + 1];
                v10 += res[(size_t)(r0 + 8) * ldc + c0];
                v11 += res[(size_t)(r0 + 8) * ldc + c0 + 1];
            }
            if (RELU) {
                v00 = fmaxf(v00, 0.f); v01 = fmaxf(v01, 0.f);
                v10 = fmaxf(v10, 0.f); v11 = fmaxf(v11, 0.f);
            }
            if (WF32) {
                C[(size_t)r0 * ldc + c0] = v00;
                C[(size_t)r0 * ldc + c0 + 1] = v01;
                C[(size_t)(r0 + 8) * ldc + c0] = v10;
                C[(size_t)(r0 + 8) * ldc + c0 + 1] = v11;
            }
            if (WPK) {
                Cp[(size_t)r0 * (ldc >> 1) + (c0 >> 1)] = sp2(v00, v01);
                Cp[(size_t)(r0 + 8) * (ldc >> 1) + (c0 >> 1)] = sp2(v10, v11);
            }
        }
}

// ---------------- GEMM kernel wrappers ----------------
__launch_bounds__(256)
__global__ void k_qkv() {
    gemm_core_p<0, 1, 0, 0, 0, 1, 1>(g_xp, g_wqkv, g_bqkv, nullptr, g_qkv, g_qkvp,
                                     Ee, Ee / 2, 1536, 1536,
                                     blockIdx.y * 128, blockIdx.x * 64);
}

__launch_bounds__(256)
__global__ void k_fc1(const float* __restrict__ bias) {
    gemm_core_p<0, 1, 1, 0, 0, 0, 1>(g_xp, g_wfc1, bias, nullptr, nullptr, g_hidp,
                                     Ee, Ee / 2, HIDh, HIDh,
                                     blockIdx.y * 128, blockIdx.x * 64);
}

__launch_bounds__(256)
__global__ void k_fc2(const float* __restrict__ bias) {
    gemm_core_p<0, 1, 0, 1, 0, 1, 0>(g_hidp, g_wfc2, bias, g_x, g_attn, nullptr,
                                     HIDh, HIDh / 2, Ee, Ee,
                                     blockIdx.y * 128, blockIdx.x * 64);
}

// ---------------- weight packing ----------------
__global__ void k_pack_qkv(const float* __restrict__ qw, const float* __restrict__ kw,
                           const float* __restrict__ vw, const float* __restrict__ qb,
                           const float* __restrict__ kb, const float* __restrict__ vb) {
    int idx = blockIdx.x * 256 + threadIdx.x;
    if (idx < (Ee / 2) * 1536) {
        int n = idx % 1536, kp = idx / 1536;
        const float* W = (n < 512) ? qw : (n < 1024 ? kw : vw);
        int c = n & 511;
        g_wqkv[idx] = sp2(W[(size_t)(2 * kp) * 512 + c], W[(size_t)(2 * kp + 1) * 512 + c]);
    }
    if (idx < 1536)
        g_bqkv[idx] = (idx < 512) ? qb[idx] : (idx < 1024 ? kb[idx - 512] : vb[idx - 1024]);
}

__global__ void k_pack_w(const float* __restrict__ W, uint2* __restrict__ out, int Kp, int N) {
    int idx = blockIdx.x * 256 + threadIdx.x;
    if (idx >= Kp * N) return;
    int n = idx % N, kp = idx / N;
    out[idx] = sp2(W[(size_t)(2 * kp) * N + n], W[(size_t)(2 * kp + 1) * N + n]);
}

// ---------------- embedding + positional encoding ----------------
__global__ void k_embed(const int* __restrict__ inp, const float* __restrict__ emb) {
    int idx = blockIdx.x * blockDim.x + threadIdx.x;
    if (idx >= Bb * Ss * (Ee / 2)) return;
    int ep = idx % (Ee / 2);
    int bs = idx / (Ee / 2);
    int s = bs % Ss;
    int tok = inp[bs];
    int e0 = 2 * ep;
    const float LN1E4 = 9.210340371976184f;
    float freq = expf(-(float)e0 * (LN1E4 / (float)Ee));
    float ang = (float)s * freq;
    float x0 = emb[(size_t)tok * Ee + e0] + sinf(ang);
    float x1 = emb[(size_t)tok * Ee + e0 + 1] + cosf(ang);
    g_x[(size_t)bs * Ee + e0] = x0;
    g_x[(size_t)bs * Ee + e0 + 1] = x1;
    g_xp[(size_t)bs * (Ee / 2) + ep] = sp2(x0, x1);
}

// ---------------- window-summed V ----------------
__global__ void k_build_vs() {
    int idx = blockIdx.x * blockDim.x + threadIdx.x;
    if (idx >= Bb * Hh * (SKk / 2) * DHh) return;
    int d = idx & 63;
    int rest = idx >> 6;
    int kp = rest % (SKk / 2);
    int bh = rest / (SKk / 2);
    int b = bh >> 3, h = bh & 7;
    const float* Vp = g_qkv + (size_t)b * Ss * 1536 + 1024 + h * DHh + d;
    int k = 2 * kp;
    float v0 = Vp[(size_t)(k + 0) * 1536];
    float v1 = Vp[(size_t)(k + 1) * 1536];
    float v2 = Vp[(size_t)(k + 2) * 1536];
    float v3 = Vp[(size_t)(k + 3) * 1536];
    float v4 = Vp[(size_t)(k + 4) * 1536];
    float v5 = Vp[(size_t)(k + 5) * 1536];
    float s0 = v0 + v1 + v2 + v3 + v4;
    float s1 = v1 + v2 + v3 + v4 + v5;
    g_vsp[((size_t)bh * (SP / 2) + kp) * DHh + d] = sp2(s0, s1);
}

// ---------------- fused attention (64-row q-tiles, 2 CTA/SM) ----------------
#define FA_OFF_Q  0                         // 32 dpair x QST2(84) uint2 = 21504
#define FA_OFF_K  21504                     // 32 x 68 uint2 = 17408
#define FA_OFF_G  38912                     // 68 x 129 floats = 35088
#define FA_OFF_P  74000                     // 32 x 68 uint2 = 17408
#define FA_OFF_V  91408                     // 32 x 68 uint2 = 17408
#define FA_OFF_S  108816                    // sFac[64] + sLf[64]
#define FA_SMEM   109328

__launch_bounds__(256)
__global__ void k_fattn() {
    extern __shared__ char dyn[];
    uint2* sQ = (uint2*)(dyn + FA_OFF_Q);
    uint2* sK = (uint2*)(dyn + FA_OFF_K);
    float* sG = (float*)(dyn + FA_OFF_G);
    uint2* sP = (uint2*)(dyn + FA_OFF_P);
    uint2* sV = (uint2*)(dyn + FA_OFF_V);
    float* sFac = (float*)(dyn + FA_OFF_S);
    float* sLf = sFac + 64;

    int qt = blockIdx.x;
    int bh = blockIdx.y;
    int b = bh >> 3, h = bh & 7;
    int q0 = qt * 64;
    const uint2* Qb = g_qkvp + (size_t)b * Ss * 768 + h * 32;
    const uint2* Kb = g_qkvp + (size_t)b * Ss * 768 + 256 + h * 32;
    const uint2* Vb = g_vsp + (size_t)bh * (SP / 2) * DHh;

    int t = threadIdx.x, lane = t & 31, wid = t >> 5;
    int wm = wid & 3, wn = wid >> 2;        // AV warp tile: 16 m x 32 n
    int g = lane >> 2, tg = lane & 3;
    float acc[4][4] = {};
    float m_run = -1e30f, l_run = 0.f;
    int srow = t >> 2, kbase = (t & 3) * 16;

    // ---- load Q tile: rows 0..67 = global q0-2..q0+65; rows 68..79 zeroed ----
    {
        int dpq = (t & 3) * 8;
        int rr = t >> 2;
#pragma unroll
        for (int rb = 0; rb < 80; rb += 64) {
            int r = rb + rr;
            if (r < 80) {
                int gr = q0 - 2 + r;
                bool ok = (r < 68) && (gr >= 0) && (gr < Ss);
#pragma unroll
                for (int u = 0; u < 8; u += 2) {
                    uint4 v = make_uint4(0, 0, 0, 0);
                    if (ok) v = *(const uint4*)(Qb + (size_t)gr * 768 + dpq + u);
                    sQ[(size_t)(dpq + u) * QST2 + r] = make_uint2(v.x, v.y);
                    sQ[(size_t)(dpq + u + 1) * QST2 + r] = make_uint2(v.z, v.w);
                }
            }
        }
    }
    // ---- load K panel 0 ----
    {
        int r = t >> 2, dpq = (t & 3) * 8;
        const uint2* src = Kb + (size_t)r * 768 + dpq;
#pragma unroll
        for (int u = 0; u < 8; u += 2) {
            uint4 v = *(const uint4*)(src + u);
            sK[(size_t)(dpq + u) * KST + r] = make_uint2(v.x, v.y);
            sK[(size_t)(dpq + u + 1) * KST + r] = make_uint2(v.z, v.w);
        }
    }
    __syncthreads();

    // ---- gram panel 0 -> ring slot 0 ----
    {
        float accg[5][4] = {};
        int nb = wid * 8 + g;
#pragma unroll
        for (int c = 0; c < 4; c++) {
            uint2 v0 = sK[(size_t)(c * 8 + tg) * KST + nb];
            uint2 v1 = sK[(size_t)(c * 8 + tg + 4) * KST + nb];
#pragma unroll
            for (int mi = 0; mi < 5; mi++) {
                int m = mi * 16 + g;
                uint2 u0 = sQ[(size_t)(c * 8 + tg) * QST2 + m];
                uint2 u1 = sQ[(size_t)(c * 8 + tg) * QST2 + m + 8];
                uint2 u2 = sQ[(size_t)(c * 8 + tg + 4) * QST2 + m];
                uint2 u3 = sQ[(size_t)(c * 8 + tg + 4) * QST2 + m + 8];
                mma16(accg[mi], u0.x, u1.x, u2.x, u3.x, v0.x, v1.x);
                mma16(accg[mi], u0.x, u1.x, u2.x, u3.x, v0.y, v1.y);
                mma16(accg[mi], u0.y, u1.y, u2.y, u3.y, v0.x, v1.x);
            }
        }
        int c0 = wid * 8 + 2 * tg;
#pragma unroll
        for (int mi = 0; mi < 5; mi++) {
            int r0 = mi * 16 + g;
            if (r0 < 68) {
                sG[r0 * GS2 + c0] = accg[mi][0] * SCALEc;
                sG[r0 * GS2 + c0 + 1] = accg[mi][1] * SCALEc;
            }
            if (r0 + 8 < 68) {
                sG[(r0 + 8) * GS2 + c0] = accg[mi][2] * SCALEc;
                sG[(r0 + 8) * GS2 + c0 + 1] = accg[mi][3] * SCALEc;
            }
        }
    }
    __syncthreads();

    // ---- k sweep ----
    for (int it = 0; it < 32; it++) {
        int k0 = it * 64;
        bool more = (it < 31);

        // load K(it+1) + V(it)
        if (more) {
            int r = t >> 2, dpq = (t & 3) * 8;
            const uint2* src = Kb + (size_t)((it + 1) * 64 + r) * 768 + dpq;
#pragma unroll
            for (int u = 0; u < 8; u += 2) {
                uint4 v = *(const uint4*)(src + u);
                sK[(size_t)(dpq + u) * KST + r] = make_uint2(v.x, v.y);
                sK[(size_t)(dpq + u + 1) * KST + r] = make_uint2(v.z, v.w);
            }
        }
        {
            int kpB = t >> 5, dB = (t & 31) * 2;
#pragma unroll
            for (int r = 0; r < 4; r++) {
                int kp = r * 8 + kpB;
                uint4 v = *(const uint4*)(Vb + (size_t)((k0 >> 1) + kp) * DHh + dB);
                sV[(size_t)kp * VST + dB] = make_uint2(v.x, v.y);
                sV[(size_t)kp * VST + dB + 1] = make_uint2(v.z, v.w);
            }
        }
        __syncthreads();   // A

        // gram(it+1) -> ring slot (it+1)&1
        if (more) {
            float accg[5][4] = {};
            int nb = wid * 8 + g;
#pragma unroll
            for (int c = 0; c < 4; c++) {
                uint2 v0 = sK[(size_t)(c * 8 + tg) * KST + nb];
                uint2 v1 = sK[(size_t)(c * 8 + tg + 4) * KST + nb];
#pragma unroll
                for (int mi = 0; mi < 5; mi++) {
                    int m = mi * 16 + g;
                    uint2 u0 = sQ[(size_t)(c * 8 + tg) * QST2 + m];
                    uint2 u1 = sQ[(size_t)(c * 8 + tg) * QST2 + m + 8];
                    uint2 u2 = sQ[(size_t)(c * 8 + tg + 4) * QST2 + m];
                    uint2 u3 = sQ[(size_t)(c * 8 + tg + 4) * QST2 + m + 8];
                    mma16(accg[mi], u0.x, u1.x, u2.x, u3.x, v0.x, v1.x);
                    mma16(accg[mi], u0.x, u1.x, u2.x, u3.x, v0.y, v1.y);
                    mma16(accg[mi], u0.y, u1.y, u2.y, u3.y, v0.x, v1.x);
                }
            }
            int c0 = ((it + 1) & 1) * 64 + wid * 8 + 2 * tg;
#pragma unroll
            for (int mi = 0; mi < 5; mi++) {
                int r0 = mi * 16 + g;
                if (r0 < 68) {
                    sG[r0 * GS2 + c0] = accg[mi][0] * SCALEc;
                    sG[r0 * GS2 + c0 + 1] = accg[mi][1] * SCALEc;
                }
                if (r0 + 8 < 68) {
                    sG[(r0 + 8) * GS2 + c0] = accg[mi][2] * SCALEc;
                    sG[(r0 + 8) * GS2 + c0 + 1] = accg[mi][3] * SCALEc;
                }
            }
        }
        __syncthreads();   // B (scores need 4-col halo of panel it+1)

        // scores: row srow, 16 k starting at kbase; quad (4 threads) per row
        float sv[16];
        float lmax = -1e30f;
#pragma unroll
        for (int i = 0; i < 16; i++) {
            int kg = k0 + kbase + i;
            float s = -1e30f;
            if (kg < SKk) {
                s = 0.f;
#pragma unroll
                for (int j = 0; j < Ww; j++)
                    s += sG[(srow + j) * GS2 + ((kg + j) & 127)];
            }
            sv[i] = s;
            lmax = fmaxf(lmax, s);
        }
        lmax = fmaxf(lmax, __shfl_xor_sync(0xffffffffu, lmax, 1));
        lmax = fmaxf(lmax, __shfl_xor_sync(0xffffffffu, lmax, 2));
        float mnew = fmaxf(m_run, lmax);
        float lsum = 0.f;
#pragma unroll
        for (int i = 0; i < 16; i += 2) {
            float p0 = __expf(sv[i] - mnew);
            float p1 = __expf(sv[i + 1] - mnew);
            lsum += p0 + p1;
            sP[(size_t)((kbase >> 1) + (i >> 1)) * PST + srow] = sp2(p0, p1);
        }
        lsum += __shfl_xor_sync(0xffffffffu, lsum, 1);
        lsum += __shfl_xor_sync(0xffffffffu, lsum, 2);
        float fac = __expf(m_run - mnew);
        l_run = l_run * fac + lsum;
        m_run = mnew;
        if ((t & 3) == 0) sFac[srow] = fac;
        __syncthreads();   // C

        // rescale + AV MMA
        {
            float f0 = sFac[wm * 16 + g];
            float f1 = sFac[wm * 16 + g + 8];
#pragma unroll
            for (int ni = 0; ni < 4; ni++) {
                acc[ni][0] *= f0; acc[ni][1] *= f0;
                acc[ni][2] *= f1; acc[ni][3] *= f1;
            }
#pragma unroll
            for (int c = 0; c < 4; c++) {
                int m = wm * 16 + g;
                uint2 u0 = sP[(size_t)(c * 8 + tg) * PST + m];
                uint2 u1 = sP[(size_t)(c * 8 + tg) * PST + m + 8];
                uint2 u2 = sP[(size_t)(c * 8 + tg + 4) * PST + m];
                uint2 u3 = sP[(size_t)(c * 8 + tg + 4) * PST + m + 8];
#pragma unroll
                for (int ni = 0; ni < 4; ni++) {
                    int n = wn * 32 + ni * 8 + g;
                    uint2 v0 = sV[(size_t)(c * 8 + tg) * VST + n];
                    uint2 v1 = sV[(size_t)(c * 8 + tg + 4) * VST + n];
                    mma16(acc[ni], u0.x, u1.x, u2.x, u3.x, v0.x, v1.x);
                    mma16(acc[ni], u0.x, u1.x, u2.x, u3.x, v0.y, v1.y);
                    mma16(acc[ni], u0.y, u1.y, u2.y, u3.y, v0.x, v1.x);
                }
            }
        }
        __syncthreads();   // F
    }

    if ((t & 3) == 0) sLf[srow] = l_run;
    __syncthreads();

    float inv0 = 1.f / sLf[wm * 16 + g];
    float inv1 = 1.f / sLf[wm * 16 + g + 8];
    float* Cb = g_attn + (size_t)b * Ss * Ee + h * DHh;
#pragma unroll
    for (int ni = 0; ni < 4; ni++) {
        int r0 = q0 + wm * 16 + g;
        int c0 = wn * 32 + ni * 8 + 2 * tg;
        Cb[(size_t)r0 * Ee + c0] = acc[ni][0] * inv0;
        Cb[(size_t)r0 * Ee + c0 + 1] = acc[ni][1] * inv0;
        Cb[(size_t)(r0 + 8) * Ee + c0] = acc[ni][2] * inv1;
        Cb[(size_t)(r0 + 8) * Ee + c0 + 1] = acc[ni][3] * inv1;
    }
}

// ---------------- LayerNorm ----------------
__launch_bounds__(256)
__global__ void k_ln(const float* __restrict__ in, const float* __restrict__ w,
                     const float* __restrict__ bz, float* __restrict__ out,
                     uint2* __restrict__ outp) {
    int row = blockIdx.x;
    const float* x = in + (size_t)row * Ee;
    __shared__ float red[256];
    int t = threadIdx.x;
    float x0 = x[2 * t], x1 = x[2 * t + 1];
    red[t] = x0 + x1; __syncthreads();
    for (int off = 128; off > 0; off >>= 1) {
        if (t < off) red[t] += red[t + off];
        __syncthreads();
    }
    float m = red[0] * (1.0f / Ee);
    __syncthreads();
    float d0 = x0 - m, d1 = x1 - m;
    red[t] = d0 * d0 + d1 * d1; __syncthreads();
    for (int off = 128; off > 0; off >>= 1) {
        if (t < off) red[t] += red[t + off];
        __syncthreads();
    }
    float inv = rsqrtf(red[0] * (1.0f / Ee) + 1e-5f);
    float y0 = d0 * inv * w[2 * t] + bz[2 * t];
    float y1 = d1 * inv * w[2 * t + 1] + bz[2 * t + 1];
    out[(size_t)row * Ee + 2 * t] = y0;
    out[(size_t)row * Ee + 2 * t + 1] = y1;
    outp[(size_t)row * (Ee / 2) + t] = sp2(y0, y1);
}

// ---------------- output head ----------------
__launch_bounds__(256)
__global__ void k_out_partial(const float* __restrict__ ow) {
    int b = blockIdx.y, c = blockIdx.x;
    const int per = (Ss * Ee) / CHUNKS;
    const float* x = g_x + (size_t)b * Ss * Ee + (size_t)c * per;
    const float* wr = ow + (size_t)c * per * OUTo;
    int t = threadIdx.x;
    float acc[OUTo] = {};
    for (int i = t; i < per; i += 256) {
        float xv = x[i];
#pragma unroll
        for (int o = 0; o < OUTo; o++) acc[o] = fmaf(xv, wr[(size_t)i * OUTo + o], acc[o]);
    }
    __shared__ float red[256 * OUTo];
#pragma unroll
    for (int o = 0; o < OUTo; o++) red[t * OUTo + o] = acc[o];
    __syncthreads();
    for (int off = 128; off > 0; off >>= 1) {
        if (t < off) {
#pragma unroll
            for (int o = 0; o < OUTo; o++)
                red[t * OUTo + o] += red[(t + off) * OUTo + o];
        }
        __syncthreads();
    }
    if (t == 0) {
#pragma unroll
        for (int o = 0; o < OUTo; o++)
            g_part[((size_t)b * CHUNKS + c) * OUTo + o] = red[o];
    }
}

__global__ void k_out_final(const float* __restrict__ ob, float* __restrict__ out) {
    int b = blockIdx.x;
    int o = threadIdx.x;
    if (o < OUTo) {
        float s = ob[o];
        for (int c = 0; c < CHUNKS; c++) s += g_part[(b * CHUNKS + c) * OUTo + o];
        out[b * OUTo + o] = s;
    }
}

// ---------------- host launcher ----------------
extern "C" void kernel_launch(void* const* d_in, const int* in_sizes, int n_in,
                              void* d_out, int out_size) {
    const int*   inputs = (const int*)d_in[0];
    const float* emb    = (const float*)d_in[1];
    const float* ln_w   = (const float*)d_in[2];
    const float* ln_b   = (const float*)d_in[3];
    const float* q_w    = (const float*)d_in[4];
    const float* q_b    = (const float*)d_in[5];
    const float* k_w    = (const float*)d_in[6];
    const float* k_b    = (const float*)d_in[7];
    const float* v_w    = (const float*)d_in[8];
    const float* v_b    = (const float*)d_in[9];
    const float* fc1_w  = (const float*)d_in[10];
    const float* fc1_b  = (const float*)d_in[11];
    const float* fc2_w  = (const float*)d_in[12];
    const float* fc2_b  = (const float*)d_in[13];
    const float* out_w  = (const float*)d_in[14];
    const float* out_b  = (const float*)d_in[15];
    float* out = (float*)d_out;

    static int smem_set = 0;
    if (!smem_set) {
        cudaFuncSetAttribute(k_fattn, cudaFuncAttributeMaxDynamicSharedMemorySize, FA_SMEM);
        smem_set = 1;
    }

    uint2 *pwfc1, *pwfc2;
    cudaGetSymbolAddress((void**)&pwfc1, g_wfc1);
    cudaGetSymbolAddress((void**)&pwfc2, g_wfc2);

    const int M = Bb * Ss;  // 4096

    k_pack_qkv<<<((Ee / 2) * 1536 + 255) / 256, 256>>>(q_w, k_w, v_w, q_b, k_b, v_b);
    k_pack_w<<<((Ee / 2) * HIDh + 255) / 256, 256>>>(fc1_w, pwfc1, Ee / 2, HIDh);
    k_pack_w<<<((HIDh / 2) * Ee + 255) / 256, 256>>>(fc2_w, pwfc2, HIDh / 2, Ee);

    k_embed<<<(Bb * Ss * (Ee / 2) + 255) / 256, 256>>>(inputs, emb);

    float *px, *pattn;
    uint2 *pxp;
    cudaGetSymbolAddress((void**)&px, g_x);
    cudaGetSymbolAddress((void**)&pattn, g_attn);
    cudaGetSymbolAddress((void**)&pxp, g_xp);

    for (int l = 0; l < Ll; l++) {
        dim3 gq(1536 / 64, M / 128);
        k_qkv<<<gq, 256>>>();

        k_build_vs<<<(Bb * Hh * (SKk / 2) * DHh + 255) / 256, 256>>>();

        dim3 gf(Ss / 64, Bb * Hh);
        k_fattn<<<gf, 256, FA_SMEM>>>();

        k_ln<<<M, 256>>>(pattn, ln_w, ln_b, px, pxp);

        dim3 g1(HIDh / 64, M / 128);
        k_fc1<<<g1, 256>>>(fc1_b);
        dim3 g2(Ee / 64, M / 128);
        k_fc2<<<g2, 256>>>(fc2_b);

        k_ln<<<M, 256>>>(pattn, ln_w, ln_b, px, pxp);
    }

    dim3 go(CHUNKS, Bb);
    k_out_partial<<<go, 256>>>(out_w);
    k_out_final<<<Bb, 32>>>(out_b, out);
}

// round 7
// speedup vs baseline: 4.4342x; 1.0627x over previous
#include <cuda_runtime.h>
#include <cuda_bf16.h>
#include <math.h>
#include <stdint.h>

#define Bb 2
#define Ss 2048
#define Ee 512
#define Hh 8
#define DHh 64
#define Ww 5
#define PADp 2
#define SKk 2044
#define HIDh 2048
#define Ll 6
#define OUTo 6
#define SCALEc 0.125f
#define CHUNKS 128
#define SP 2048

#define AST 132   // smem A row stride (uint2)
#define BST 68    // smem B row stride (uint2), 64-wide core
#define BSW 132   // smem B row stride (uint2), 128-wide core
// fattn strides
#define QST2 84
#define KST 68
#define PST 68
#define VST 68
#define GS2 132   // G ring row stride (floats); mult of 4 -> aligned float4 loads

// ---------------- scratch ----------------
__device__ float g_x[Bb * Ss * Ee];
__device__ uint2 g_xp[Bb * Ss * (Ee / 2)];
__device__ uint2 g_qkvp[Bb * Ss * 768];
__device__ uint2 g_hidp[(size_t)Bb * Ss * (HIDh / 2)];
__device__ uint2 g_vsp[(size_t)Bb * Hh * (SP / 2) * DHh];
__device__ float g_attn[Bb * Ss * Ee];
__device__ float g_part[Bb * CHUNKS * OUTo];
__device__ uint2 g_wqkv[(Ee / 2) * 1536];
__device__ float g_bqkv[1536];
__device__ uint2 g_wfc1[(Ee / 2) * HIDh];
__device__ uint2 g_wfc2[(HIDh / 2) * Ee];

// ---------------- bf16 split/pack ----------------
__device__ __forceinline__ uint2 sp2(float x, float y) {
    __nv_bfloat16 xh = __float2bfloat16_rn(x);
    __nv_bfloat16 yh = __float2bfloat16_rn(y);
    float xr = x - __bfloat162float(xh);
    float yr = y - __bfloat162float(yh);
    __nv_bfloat16 xl = __float2bfloat16_rn(xr);
    __nv_bfloat16 yl = __float2bfloat16_rn(yr);
    uint2 w;
    w.x = ((uint32_t)__bfloat16_as_ushort(yh) << 16) | (uint32_t)__bfloat16_as_ushort(xh);
    w.y = ((uint32_t)__bfloat16_as_ushort(yl) << 16) | (uint32_t)__bfloat16_as_ushort(xl);
    return w;
}

__device__ __forceinline__ float blo(uint32_t u) {
    return __bfloat162float(__ushort_as_bfloat16((unsigned short)(u & 0xffffu)));
}
__device__ __forceinline__ float bhi(uint32_t u) {
    return __bfloat162float(__ushort_as_bfloat16((unsigned short)(u >> 16)));
}

__device__ __forceinline__ void mma16(float c[4], uint32_t a0, uint32_t a1, uint32_t a2,
                                      uint32_t a3, uint32_t b0, uint32_t b1) {
    asm volatile(
        "mma.sync.aligned.m16n8k16.row.col.f32.bf16.bf16.f32 "
        "{%0,%1,%2,%3},{%4,%5,%6,%7},{%8,%9},{%0,%1,%2,%3};"
        : "+f"(c[0]), "+f"(c[1]), "+f"(c[2]), "+f"(c[3])
        : "r"(a0), "r"(a1), "r"(a2), "r"(a3), "r"(b0), "r"(b1));
}

// one 16-k chunk over 128x64 tile (warp tile 32x32) -- used by 64-wide core
__device__ __forceinline__ void mma_chunk(const uint2* sA, const uint2* sB,
                                          int wm, int wn, int lane, float acc[2][4][4]) {
    int g = lane >> 2, tg = lane & 3;
    uint32_t ah[2][4], al[2][4];
#pragma unroll
    for (int mi = 0; mi < 2; mi++) {
        int m = wm * 32 + mi * 16 + g;
        uint2 u0 = sA[(size_t)tg * AST + m];
        uint2 u1 = sA[(size_t)tg * AST + m + 8];
        uint2 u2 = sA[(size_t)(tg + 4) * AST + m];
        uint2 u3 = sA[(size_t)(tg + 4) * AST + m + 8];
        ah[mi][0] = u0.x; al[mi][0] = u0.y;
        ah[mi][1] = u1.x; al[mi][1] = u1.y;
        ah[mi][2] = u2.x; al[mi][2] = u2.y;
        ah[mi][3] = u3.x; al[mi][3] = u3.y;
    }
#pragma unroll
    for (int ni = 0; ni < 4; ni++) {
        int n = wn * 32 + ni * 8 + g;
        uint2 v0 = sB[(size_t)tg * BST + n];
        uint2 v1 = sB[(size_t)(tg + 4) * BST + n];
#pragma unroll
        for (int mi = 0; mi < 2; mi++) {
            mma16(acc[mi][ni], ah[mi][0], ah[mi][1], ah[mi][2], ah[mi][3], v0.x, v1.x);
            mma16(acc[mi][ni], ah[mi][0], ah[mi][1], ah[mi][2], ah[mi][3], v0.y, v1.y);
            mma16(acc[mi][ni], al[mi][0], al[mi][1], al[mi][2], al[mi][3], v0.x, v1.x);
        }
    }
}

// ---------------- 64-wide packed GEMM core (fc2) ----------------
template <int BIAS, int RELU, int RES, int WF32, int WPK>
__device__ __forceinline__ void gemm_core_p(
    const uint2* __restrict__ A, const uint2* __restrict__ B,
    const float* __restrict__ bias, const float* __restrict__ res,
    float* __restrict__ C, uint2* __restrict__ Cp,
    int K, int lda2, int ldb2, int ldc, int bm, int bn) {
    __shared__ uint2 sA[2][8 * AST];
    __shared__ uint2 sB[2][8 * BST];
    int t = threadIdx.x, lane = t & 31, wid = t >> 5;
    int wm = wid & 3, wn = wid >> 2;
    float acc[2][4][4] = {};

    int mA = t & 127, koA2 = (t >> 7) * 4;
    const uint2* Arow = A + (size_t)(bm + mA) * lda2 + koA2;
    int kpB = t >> 5, nB = (t & 31) * 2;
    const uint2* Bp = B + (size_t)kpB * ldb2 + bn + nB;

    uint4 a0 = *(const uint4*)(Arow);
    uint4 a1 = *(const uint4*)(Arow + 2);
    uint4 b0 = *(const uint4*)(Bp);

    {
        uint2* pa = sA[0];
        pa[(size_t)(koA2 + 0) * AST + mA] = make_uint2(a0.x, a0.y);
        pa[(size_t)(koA2 + 1) * AST + mA] = make_uint2(a0.z, a0.w);
        pa[(size_t)(koA2 + 2) * AST + mA] = make_uint2(a1.x, a1.y);
        pa[(size_t)(koA2 + 3) * AST + mA] = make_uint2(a1.z, a1.w);
        uint2* pb = sB[0];
        pb[(size_t)kpB * BST + nB]     = make_uint2(b0.x, b0.y);
        pb[(size_t)kpB * BST + nB + 1] = make_uint2(b0.z, b0.w);
    }
    __syncthreads();

    int nch = K >> 4;
    for (int ch = 0; ch < nch; ch++) {
        int s = ch & 1;
        bool more = (ch + 1 < nch);
        if (more) {
            int off = (ch + 1) * 8;
            a0 = *(const uint4*)(Arow + off);
            a1 = *(const uint4*)(Arow + off + 2);
            b0 = *(const uint4*)(Bp + (size_t)(ch + 1) * 8 * ldb2);
        }
        mma_chunk(sA[s], sB[s], wm, wn, lane, acc);
        if (more) {
            int s2 = s ^ 1;
            uint2* pa = sA[s2];
            pa[(size_t)(koA2 + 0) * AST + mA] = make_uint2(a0.x, a0.y);
            pa[(size_t)(koA2 + 1) * AST + mA] = make_uint2(a0.z, a0.w);
            pa[(size_t)(koA2 + 2) * AST + mA] = make_uint2(a1.x, a1.y);
            pa[(size_t)(koA2 + 3) * AST + mA] = make_uint2(a1.z, a1.w);
            uint2* pb = sB[s2];
            pb[(size_t)kpB * BST + nB]     = make_uint2(b0.x, b0.y);
            pb[(size_t)kpB * BST + nB + 1] = make_uint2(b0.z, b0.w);
        }
        __syncthreads();
    }

    int g = lane >> 2, tg = lane & 3;
#pragma unroll
    for (int mi = 0; mi < 2; mi++)
#pragma unroll
        for (int ni = 0; ni < 4; ni++) {
            int r0 = bm + wm * 32 + mi * 16 + g;
            int c0 = bn + wn * 32 + ni * 8 + 2 * tg;
            float v00 = acc[mi][ni][0], v01 = acc[mi][ni][1];
            float v10 = acc[mi][ni][2], v11 = acc[mi][ni][3];
            if (BIAS) {
                float bv0 = bias[c0], bv1 = bias[c0 + 1];
                v00 += bv0; v01 += bv1; v10 += bv0; v11 += bv1;
            }
            if (RES) {
                v00 += res[(size_t)r0 * ldc + c0];
                v01 += res[(size_t)r0 * ldc + c0 + 1];
                v10 += res[(size_t)(r0 + 8) * ldc + c0];
                v11 += res[(size_t)(r0 + 8) * ldc + c0 + 1];
            }
            if (RELU) {
                v00 = fmaxf(v00, 0.f); v01 = fmaxf(v01, 0.f);
                v10 = fmaxf(v10, 0.f); v11 = fmaxf(v11, 0.f);
            }
            if (WF32) {
                C[(size_t)r0 * ldc + c0] = v00;
                C[(size_t)r0 * ldc + c0 + 1] = v01;
                C[(size_t)(r0 + 8) * ldc + c0] = v10;
                C[(size_t)(r0 + 8) * ldc + c0 + 1] = v11;
            }
            if (WPK) {
                Cp[(size_t)r0 * (ldc >> 1) + (c0 >> 1)] = sp2(v00, v01);
                Cp[(size_t)(r0 + 8) * (ldc >> 1) + (c0 >> 1)] = sp2(v10, v11);
            }
        }
}

__launch_bounds__(256)
__global__ void k_fc2(const float* __restrict__ bias) {
    gemm_core_p<1, 0, 1, 1, 0>(g_hidp, g_wfc2, bias, g_x, g_attn, nullptr,
                               HIDh, HIDh / 2, Ee, Ee,
                               blockIdx.y * 128, blockIdx.x * 64);
}

// ---------------- 128x128 packed GEMM (qkv, fc1) ----------------
template <int BIAS, int RELU, int WPK>
__launch_bounds__(256, 2)
__global__ void k_gemm128(const uint2* __restrict__ A, const uint2* __restrict__ B,
                          const float* __restrict__ bias,
                          uint2* __restrict__ Cp,
                          int K, int lda2, int ldb2, int ldc) {
    __shared__ uint2 sA[2][8 * AST];
    __shared__ uint2 sB2[2][8 * BSW];
    int t = threadIdx.x, lane = t & 31, wid = t >> 5;
    int wm = wid & 3, wn = wid >> 2;
    int g = lane >> 2, tg = lane & 3;
    int bm = blockIdx.y * 128, bn = blockIdx.x * 128;
    float acc[2][8][4] = {};

    int mA = t & 127, koA2 = (t >> 7) * 4;
    const uint2* Arow = A + (size_t)(bm + mA) * lda2 + koA2;
    int kpB = t >> 5, nB = (t & 31) * 4;
    const uint2* Bp = B + (size_t)kpB * ldb2 + bn + nB;

    uint4 a0 = *(const uint4*)(Arow);
    uint4 a1 = *(const uint4*)(Arow + 2);
    uint4 b0 = *(const uint4*)(Bp);
    uint4 b1 = *(const uint4*)(Bp + 2);

    {
        uint2* pa = sA[0];
        pa[(size_t)(koA2 + 0) * AST + mA] = make_uint2(a0.x, a0.y);
        pa[(size_t)(koA2 + 1) * AST + mA] = make_uint2(a0.z, a0.w);
        pa[(size_t)(koA2 + 2) * AST + mA] = make_uint2(a1.x, a1.y);
        pa[(size_t)(koA2 + 3) * AST + mA] = make_uint2(a1.z, a1.w);
        uint2* pb = sB2[0];
        pb[(size_t)kpB * BSW + nB]     = make_uint2(b0.x, b0.y);
        pb[(size_t)kpB * BSW + nB + 1] = make_uint2(b0.z, b0.w);
        pb[(size_t)kpB * BSW + nB + 2] = make_uint2(b1.x, b1.y);
        pb[(size_t)kpB * BSW + nB + 3] = make_uint2(b1.z, b1.w);
    }
    __syncthreads();

    int nch = K >> 4;
    for (int ch = 0; ch < nch; ch++) {
        int s = ch & 1;
        bool more = (ch + 1 < nch);
        if (more) {
            int off = (ch + 1) * 8;
            a0 = *(const uint4*)(Arow + off);
            a1 = *(const uint4*)(Arow + off + 2);
            const uint2* Bn = Bp + (size_t)(ch + 1) * 8 * ldb2;
            b0 = *(const uint4*)(Bn);
            b1 = *(const uint4*)(Bn + 2);
        }
        {
            const uint2* pa = sA[s];
            const uint2* pb = sB2[s];
            uint32_t ah[2][4], al[2][4];
#pragma unroll
            for (int mi = 0; mi < 2; mi++) {
                int m = wm * 32 + mi * 16 + g;
                uint2 u0 = pa[(size_t)tg * AST + m];
                uint2 u1 = pa[(size_t)tg * AST + m + 8];
                uint2 u2 = pa[(size_t)(tg + 4) * AST + m];
                uint2 u3 = pa[(size_t)(tg + 4) * AST + m + 8];
                ah[mi][0] = u0.x; al[mi][0] = u0.y;
                ah[mi][1] = u1.x; al[mi][1] = u1.y;
                ah[mi][2] = u2.x; al[mi][2] = u2.y;
                ah[mi][3] = u3.x; al[mi][3] = u3.y;
            }
#pragma unroll
            for (int ni = 0; ni < 8; ni++) {
                int n = wn * 64 + ni * 8 + g;
                uint2 v0 = pb[(size_t)tg * BSW + n];
                uint2 v1 = pb[(size_t)(tg + 4) * BSW + n];
#pragma unroll
                for (int mi = 0; mi < 2; mi++) {
                    mma16(acc[mi][ni], ah[mi][0], ah[mi][1], ah[mi][2], ah[mi][3], v0.x, v1.x);
                    mma16(acc[mi][ni], ah[mi][0], ah[mi][1], ah[mi][2], ah[mi][3], v0.y, v1.y);
                    mma16(acc[mi][ni], al[mi][0], al[mi][1], al[mi][2], al[mi][3], v0.x, v1.x);
                }
            }
        }
        if (more) {
            int s2 = s ^ 1;
            uint2* pa = sA[s2];
            pa[(size_t)(koA2 + 0) * AST + mA] = make_uint2(a0.x, a0.y);
            pa[(size_t)(koA2 + 1) * AST + mA] = make_uint2(a0.z, a0.w);
            pa[(size_t)(koA2 + 2) * AST + mA] = make_uint2(a1.x, a1.y);
            pa[(size_t)(koA2 + 3) * AST + mA] = make_uint2(a1.z, a1.w);
            uint2* pb = sB2[s2];
            pb[(size_t)kpB * BSW + nB]     = make_uint2(b0.x, b0.y);
            pb[(size_t)kpB * BSW + nB + 1] = make_uint2(b0.z, b0.w);
            pb[(size_t)kpB * BSW + nB + 2] = make_uint2(b1.x, b1.y);
            pb[(size_t)kpB * BSW + nB + 3] = make_uint2(b1.z, b1.w);
        }
        __syncthreads();
    }

#pragma unroll
    for (int mi = 0; mi < 2; mi++)
#pragma unroll
        for (int ni = 0; ni < 8; ni++) {
            int r0 = bm + wm * 32 + mi * 16 + g;
            int c0 = bn + wn * 64 + ni * 8 + 2 * tg;
            float v00 = acc[mi][ni][0], v01 = acc[mi][ni][1];
            float v10 = acc[mi][ni][2], v11 = acc[mi][ni][3];
            if (BIAS) {
                float bv0 = bias[c0], bv1 = bias[c0 + 1];
                v00 += bv0; v01 += bv1; v10 += bv0; v11 += bv1;
            }
            if (RELU) {
                v00 = fmaxf(v00, 0.f); v01 = fmaxf(v01, 0.f);
                v10 = fmaxf(v10, 0.f); v11 = fmaxf(v11, 0.f);
            }
            if (WPK) {
                Cp[(size_t)r0 * (ldc >> 1) + (c0 >> 1)] = sp2(v00, v01);
                Cp[(size_t)(r0 + 8) * (ldc >> 1) + (c0 >> 1)] = sp2(v10, v11);
            }
        }
}

// ---------------- weight packing ----------------
__global__ void k_pack_qkv(const float* __restrict__ qw, const float* __restrict__ kw,
                           const float* __restrict__ vw, const float* __restrict__ qb,
                           const float* __restrict__ kb, const float* __restrict__ vb) {
    int idx = blockIdx.x * 256 + threadIdx.x;
    if (idx < (Ee / 2) * 1536) {
        int n = idx % 1536, kp = idx / 1536;
        const float* W = (n < 512) ? qw : (n < 1024 ? kw : vw);
        int c = n & 511;
        g_wqkv[idx] = sp2(W[(size_t)(2 * kp) * 512 + c], W[(size_t)(2 * kp + 1) * 512 + c]);
    }
    if (idx < 1536)
        g_bqkv[idx] = (idx < 512) ? qb[idx] : (idx < 1024 ? kb[idx - 512] : vb[idx - 1024]);
}

__global__ void k_pack_w(const float* __restrict__ W, uint2* __restrict__ out, int Kp, int N) {
    int idx = blockIdx.x * 256 + threadIdx.x;
    if (idx >= Kp * N) return;
    int n = idx % N, kp = idx / N;
    out[idx] = sp2(W[(size_t)(2 * kp) * N + n], W[(size_t)(2 * kp + 1) * N + n]);
}

// ---------------- embedding + positional encoding ----------------
__global__ void k_embed(const int* __restrict__ inp, const float* __restrict__ emb) {
    int idx = blockIdx.x * blockDim.x + threadIdx.x;
    if (idx >= Bb * Ss * (Ee / 2)) return;
    int ep = idx % (Ee / 2);
    int bs = idx / (Ee / 2);
    int s = bs % Ss;
    int tok = inp[bs];
    int e0 = 2 * ep;
    const float LN1E4 = 9.210340371976184f;
    float freq = expf(-(float)e0 * (LN1E4 / (float)Ee));
    float ang = (float)s * freq;
    float x0 = emb[(size_t)tok * Ee + e0] + sinf(ang);
    float x1 = emb[(size_t)tok * Ee + e0 + 1] + cosf(ang);
    g_x[(size_t)bs * Ee + e0] = x0;
    g_x[(size_t)bs * Ee + e0 + 1] = x1;
    g_xp[(size_t)bs * (Ee / 2) + ep] = sp2(x0, x1);
}

// ---------------- window-summed V from packed QKV ----------------
__global__ void k_build_vs() {
    int idx = blockIdx.x * blockDim.x + threadIdx.x;   // bh x kp x dpair
    if (idx >= Bb * Hh * (SKk / 2) * (DHh / 2)) return;
    int dp = idx & 31;
    int rest = idx >> 5;
    int kp = rest % (SKk / 2);
    int bh = rest / (SKk / 2);
    int b = bh >> 3, h = bh & 7;
    const uint2* Vp = g_qkvp + (size_t)b * Ss * 768 + 512 + h * 32 + dp;
    int k = 2 * kp;
    float v0[6], v1[6];
#pragma unroll
    for (int r = 0; r < 6; r++) {
        uint2 w = Vp[(size_t)(k + r) * 768];
        v0[r] = blo(w.x) + blo(w.y);
        v1[r] = bhi(w.x) + bhi(w.y);
    }
    float s00 = v0[0] + v0[1] + v0[2] + v0[3] + v0[4];
    float s10 = v0[1] + v0[2] + v0[3] + v0[4] + v0[5];
    float s01 = v1[0] + v1[1] + v1[2] + v1[3] + v1[4];
    float s11 = v1[1] + v1[2] + v1[3] + v1[4] + v1[5];
    uint2* dst = g_vsp + ((size_t)bh * (SP / 2) + kp) * DHh + 2 * dp;
    dst[0] = sp2(s00, s10);
    dst[1] = sp2(s01, s11);
}

// ---------------- fused attention (64-row q-tiles) ----------------
#define FA_OFF_Q  0                          // 32 x 84 uint2  = 21504
#define FA_OFF_K  21504                      // 32 x 68 uint2  = 17408
#define FA_OFF_G  38912                      // 68 x 132 float = 35904
#define FA_OFF_P  74816                      // 32 x 68 uint2  = 17408
#define FA_OFF_V  92224                      // 32 x 68 uint2  = 17408
#define FA_OFF_S  109632                     // sFac[64] + sLf[64]
#define FA_SMEM   110144

__launch_bounds__(256)
__global__ void k_fattn() {
    extern __shared__ char dyn[];
    uint2* sQ = (uint2*)(dyn + FA_OFF_Q);
    uint2* sK = (uint2*)(dyn + FA_OFF_K);
    float* sG = (float*)(dyn + FA_OFF_G);
    uint2* sP = (uint2*)(dyn + FA_OFF_P);
    uint2* sV = (uint2*)(dyn + FA_OFF_V);
    float* sFac = (float*)(dyn + FA_OFF_S);
    float* sLf = sFac + 64;

    int qt = blockIdx.x;
    int bh = blockIdx.y;
    int b = bh >> 3, h = bh & 7;
    int q0 = qt * 64;
    const uint2* Qb = g_qkvp + (size_t)b * Ss * 768 + h * 32;
    const uint2* Kb = g_qkvp + (size_t)b * Ss * 768 + 256 + h * 32;
    const uint2* Vb = g_vsp + (size_t)bh * (SP / 2) * DHh;

    int t = threadIdx.x, lane = t & 31, wid = t >> 5;
    int wm = wid & 3, wn = wid >> 2;
    int g = lane >> 2, tg = lane & 3;
    float acc[4][4] = {};
    float m_run = -1e30f, l_run = 0.f;
    int srow = t >> 2, kbase = (t & 3) * 16;

    // load Q tile: rows 0..67 = global q0-2..q0+65; rows 68..79 zero
    {
        int dpq = (t & 3) * 8;
        int rr = t >> 2;
#pragma unroll
        for (int rb = 0; rb < 80; rb += 64) {
            int r = rb + rr;
            if (r < 80) {
                int gr = q0 - 2 + r;
                bool ok = (r < 68) && (gr >= 0) && (gr < Ss);
#pragma unroll
                for (int u = 0; u < 8; u += 2) {
                    uint4 v = make_uint4(0, 0, 0, 0);
                    if (ok) v = *(const uint4*)(Qb + (size_t)gr * 768 + dpq + u);
                    sQ[(size_t)(dpq + u) * QST2 + r] = make_uint2(v.x, v.y);
                    sQ[(size_t)(dpq + u + 1) * QST2 + r] = make_uint2(v.z, v.w);
                }
            }
        }
    }
    // load K panel 0
    {
        int r = t >> 2, dpq = (t & 3) * 8;
        const uint2* src = Kb + (size_t)r * 768 + dpq;
#pragma unroll
        for (int u = 0; u < 8; u += 2) {
            uint4 v = *(const uint4*)(src + u);
            sK[(size_t)(dpq + u) * KST + r] = make_uint2(v.x, v.y);
            sK[(size_t)(dpq + u + 1) * KST + r] = make_uint2(v.z, v.w);
        }
    }
    __syncthreads();

    // gram panel 0 -> ring slot 0
    {
        float accg[5][4] = {};
        int nb = wid * 8 + g;
#pragma unroll
        for (int c = 0; c < 4; c++) {
            uint2 v0 = sK[(size_t)(c * 8 + tg) * KST + nb];
            uint2 v1 = sK[(size_t)(c * 8 + tg + 4) * KST + nb];
#pragma unroll
            for (int mi = 0; mi < 5; mi++) {
                int m = mi * 16 + g;
                uint2 u0 = sQ[(size_t)(c * 8 + tg) * QST2 + m];
                uint2 u1 = sQ[(size_t)(c * 8 + tg) * QST2 + m + 8];
                uint2 u2 = sQ[(size_t)(c * 8 + tg + 4) * QST2 + m];
                uint2 u3 = sQ[(size_t)(c * 8 + tg + 4) * QST2 + m + 8];
                mma16(accg[mi], u0.x, u1.x, u2.x, u3.x, v0.x, v1.x);
                mma16(accg[mi], u0.x, u1.x, u2.x, u3.x, v0.y, v1.y);
                mma16(accg[mi], u0.y, u1.y, u2.y, u3.y, v0.x, v1.x);
            }
        }
        int c0 = wid * 8 + 2 * tg;
#pragma unroll
        for (int mi = 0; mi < 5; mi++) {
            int r0 = mi * 16 + g;
            if (r0 < 68) {
                sG[r0 * GS2 + c0] = accg[mi][0] * SCALEc;
                sG[r0 * GS2 + c0 + 1] = accg[mi][1] * SCALEc;
            }
            if (r0 + 8 < 68) {
                sG[(r0 + 8) * GS2 + c0] = accg[mi][2] * SCALEc;
                sG[(r0 + 8) * GS2 + c0 + 1] = accg[mi][3] * SCALEc;
            }
        }
    }
    __syncthreads();

    for (int it = 0; it < 32; it++) {
        int k0 = it * 64;
        bool more = (it < 31);

        if (more) {
            int r = t >> 2, dpq = (t & 3) * 8;
            const uint2* src = Kb + (size_t)((it + 1) * 64 + r) * 768 + dpq;
#pragma unroll
            for (int u = 0; u < 8; u += 2) {
                uint4 v = *(const uint4*)(src + u);
                sK[(size_t)(dpq + u) * KST + r] = make_uint2(v.x, v.y);
                sK[(size_t)(dpq + u + 1) * KST + r] = make_uint2(v.z, v.w);
            }
        }
        {
            int kpB = t >> 5, dB = (t & 31) * 2;
#pragma unroll
            for (int r = 0; r < 4; r++) {
                int kp = r * 8 + kpB;
                uint4 v = *(const uint4*)(Vb + (size_t)((k0 >> 1) + kp) * DHh + dB);
                sV[(size_t)kp * VST + dB] = make_uint2(v.x, v.y);
                sV[(size_t)kp * VST + dB + 1] = make_uint2(v.z, v.w);
            }
        }
        __syncthreads();   // A

        if (more) {
            float accg[5][4] = {};
            int nb = wid * 8 + g;
#pragma unroll
            for (int c = 0; c < 4; c++) {
                uint2 v0 = sK[(size_t)(c * 8 + tg) * KST + nb];
                uint2 v1 = sK[(size_t)(c * 8 + tg + 4) * KST + nb];
#pragma unroll
                for (int mi = 0; mi < 5; mi++) {
                    int m = mi * 16 + g;
                    uint2 u0 = sQ[(size_t)(c * 8 + tg) * QST2 + m];
                    uint2 u1 = sQ[(size_t)(c * 8 + tg) * QST2 + m + 8];
                    uint2 u2 = sQ[(size_t)(c * 8 + tg + 4) * QST2 + m];
                    uint2 u3 = sQ[(size_t)(c * 8 + tg + 4) * QST2 + m + 8];
                    mma16(accg[mi], u0.x, u1.x, u2.x, u3.x, v0.x, v1.x);
                    mma16(accg[mi], u0.x, u1.x, u2.x, u3.x, v0.y, v1.y);
                    mma16(accg[mi], u0.y, u1.y, u2.y, u3.y, v0.x, v1.x);
                }
            }
            int c0 = ((it + 1) & 1) * 64 + wid * 8 + 2 * tg;
#pragma unroll
            for (int mi = 0; mi < 5; mi++) {
                int r0 = mi * 16 + g;
                if (r0 < 68) {
                    sG[r0 * GS2 + c0] = accg[mi][0] * SCALEc;
                    sG[r0 * GS2 + c0 + 1] = accg[mi][1] * SCALEc;
                }
                if (r0 + 8 < 68) {
                    sG[(r0 + 8) * GS2 + c0] = accg[mi][2] * SCALEc;
                    sG[(r0 + 8) * GS2 + c0 + 1] = accg[mi][3] * SCALEc;
                }
            }
        }
        __syncthreads();   // B

        // scores: vectorized shift-sum (5 rows x 5 float4 + register shifts)
        float sv[16];
#pragma unroll
        for (int i = 0; i < 16; i++) sv[i] = 0.f;
        int cb0 = ((it & 1) << 6) + kbase;
#pragma unroll
        for (int j = 0; j < Ww; j++) {
            const float* rp = sG + (srow + j) * GS2;
            float rr[20];
#pragma unroll
            for (int m = 0; m < 5; m++) {
                float4 v = *(const float4*)(rp + ((cb0 + 4 * m) & 127));
                rr[4 * m + 0] = v.x; rr[4 * m + 1] = v.y;
                rr[4 * m + 2] = v.z; rr[4 * m + 3] = v.w;
            }
#pragma unroll
            for (int i = 0; i < 16; i++) sv[i] += rr[i + j];
        }
        float lmax = -1e30f;
#pragma unroll
        for (int i = 0; i < 16; i++) {
            if (k0 + kbase + i >= SKk) sv[i] = -1e30f;
            lmax = fmaxf(lmax, sv[i]);
        }
        lmax = fmaxf(lmax, __shfl_xor_sync(0xffffffffu, lmax, 1));
        lmax = fmaxf(lmax, __shfl_xor_sync(0xffffffffu, lmax, 2));
        float mnew = fmaxf(m_run, lmax);
        float lsum = 0.f;
#pragma unroll
        for (int i = 0; i < 16; i += 2) {
            float p0 = __expf(sv[i] - mnew);
            float p1 = __expf(sv[i + 1] - mnew);
            lsum += p0 + p1;
            sP[(size_t)((kbase >> 1) + (i >> 1)) * PST + srow] = sp2(p0, p1);
        }
        lsum += __shfl_xor_sync(0xffffffffu, lsum, 1);
        lsum += __shfl_xor_sync(0xffffffffu, lsum, 2);
        float fac = __expf(m_run - mnew);
        l_run = l_run * fac + lsum;
        m_run = mnew;
        if ((t & 3) == 0) sFac[srow] = fac;
        __syncthreads();   // C

        {
            float f0 = sFac[wm * 16 + g];
            float f1 = sFac[wm * 16 + g + 8];
#pragma unroll
            for (int ni = 0; ni < 4; ni++) {
                acc[ni][0] *= f0; acc[ni][1] *= f0;
                acc[ni][2] *= f1; acc[ni][3] *= f1;
            }
#pragma unroll
            for (int c = 0; c < 4; c++) {
                int m = wm * 16 + g;
                uint2 u0 = sP[(size_t)(c * 8 + tg) * PST + m];
                uint2 u1 = sP[(size_t)(c * 8 + tg) * PST + m + 8];
                uint2 u2 = sP[(size_t)(c * 8 + tg + 4) * PST + m];
                uint2 u3 = sP[(size_t)(c * 8 + tg + 4) * PST + m + 8];
#pragma unroll
                for (int ni = 0; ni < 4; ni++) {
                    int n = wn * 32 + ni * 8 + g;
                    uint2 v0 = sV[(size_t)(c * 8 + tg) * VST + n];
                    uint2 v1 = sV[(size_t)(c * 8 + tg + 4) * VST + n];
                    mma16(acc[ni], u0.x, u1.x, u2.x, u3.x, v0.x, v1.x);
                    mma16(acc[ni], u0.x, u1.x, u2.x, u3.x, v0.y, v1.y);
                    mma16(acc[ni], u0.y, u1.y, u2.y, u3.y, v0.x, v1.x);
                }
            }
        }
        __syncthreads();   // D
    }

    if ((t & 3) == 0) sLf[srow] = l_run;
    __syncthreads();

    float inv0 = 1.f / sLf[wm * 16 + g];
    float inv1 = 1.f / sLf[wm * 16 + g + 8];
    float* Cb = g_attn + (size_t)b * Ss * Ee + h * DHh;
#pragma unroll
    for (int ni = 0; ni < 4; ni++) {
        int r0 = q0 + wm * 16 + g;
        int c0 = wn * 32 + ni * 8 + 2 * tg;
        Cb[(size_t)r0 * Ee + c0] = acc[ni][0] * inv0;
        Cb[(size_t)r0 * Ee + c0 + 1] = acc[ni][1] * inv0;
        Cb[(size_t)(r0 + 8) * Ee + c0] = acc[ni][2] * inv1;
        Cb[(size_t)(r0 + 8) * Ee + c0 + 1] = acc[ni][3] * inv1;
    }
}

// ---------------- LayerNorm ----------------
__launch_bounds__(256)
__global__ void k_ln(const float* __restrict__ in, const float* __restrict__ w,
                     const float* __restrict__ bz, float* __restrict__ out,
                     uint2* __restrict__ outp) {
    int row = blockIdx.x;
    const float* x = in + (size_t)row * Ee;
    __shared__ float red[256];
    int t = threadIdx.x;
    float x0 = x[2 * t], x1 = x[2 * t + 1];
    red[t] = x0 + x1; __syncthreads();
    for (int off = 128; off > 0; off >>= 1) {
        if (t < off) red[t] += red[t + off];
        __syncthreads();
    }
    float m = red[0] * (1.0f / Ee);
    __syncthreads();
    float d0 = x0 - m, d1 = x1 - m;
    red[t] = d0 * d0 + d1 * d1; __syncthreads();
    for (int off = 128; off > 0; off >>= 1) {
        if (t < off) red[t] += red[t + off];
        __syncthreads();
    }
    float inv = rsqrtf(red[0] * (1.0f / Ee) + 1e-5f);
    float y0 = d0 * inv * w[2 * t] + bz[2 * t];
    float y1 = d1 * inv * w[2 * t + 1] + bz[2 * t + 1];
    out[(size_t)row * Ee + 2 * t] = y0;
    out[(size_t)row * Ee + 2 * t + 1] = y1;
    outp[(size_t)row * (Ee / 2) + t] = sp2(y0, y1);
}

// ---------------- output head ----------------
__launch_bounds__(256)
__global__ void k_out_partial(const float* __restrict__ ow) {
    int b = blockIdx.y, c = blockIdx.x;
    const int per = (Ss * Ee) / CHUNKS;
    const float* x = g_x + (size_t)b * Ss * Ee + (size_t)c * per;
    const float* wr = ow + (size_t)c * per * OUTo;
    int t = threadIdx.x;
    float acc[OUTo] = {};
    for (int i = t; i < per; i += 256) {
        float xv = x[i];
#pragma unroll
        for (int o = 0; o < OUTo; o++) acc[o] = fmaf(xv, wr[(size_t)i * OUTo + o], acc[o]);
    }
    __shared__ float red[256 * OUTo];
#pragma unroll
    for (int o = 0; o < OUTo; o++) red[t * OUTo + o] = acc[o];
    __syncthreads();
    for (int off = 128; off > 0; off >>= 1) {
        if (t < off) {
#pragma unroll
            for (int o = 0; o < OUTo; o++)
                red[t * OUTo + o] += red[(t + off) * OUTo + o];
        }
        __syncthreads();
    }
    if (t == 0) {
#pragma unroll
        for (int o = 0; o < OUTo; o++)
            g_part[((size_t)b * CHUNKS + c) * OUTo + o] = red[o];
    }
}

__global__ void k_out_final(const float* __restrict__ ob, float* __restrict__ out) {
    int b = blockIdx.x;
    int o = threadIdx.x;
    if (o < OUTo) {
        float s = ob[o];
        for (int c = 0; c < CHUNKS; c++) s += g_part[(b * CHUNKS + c) * OUTo + o];
        out[b * OUTo + o] = s;
    }
}

// ---------------- host launcher ----------------
extern "C" void kernel_launch(void* const* d_in, const int* in_sizes, int n_in,
                              void* d_out, int out_size) {
    const int*   inputs = (const int*)d_in[0];
    const float* emb    = (const float*)d_in[1];
    const float* ln_w   = (const float*)d_in[2];
    const float* ln_b   = (const float*)d_in[3];
    const float* q_w    = (const float*)d_in[4];
    const float* q_b    = (const float*)d_in[5];
    const float* k_w    = (const float*)d_in[6];
    const float* k_b    = (const float*)d_in[7];
    const float* v_w    = (const float*)d_in[8];
    const float* v_b    = (const float*)d_in[9];
    const float* fc1_w  = (const float*)d_in[10];
    const float* fc1_b  = (const float*)d_in[11];
    const float* fc2_w  = (const float*)d_in[12];
    const float* fc2_b  = (const float*)d_in[13];
    const float* out_w  = (const float*)d_in[14];
    const float* out_b  = (const float*)d_in[15];
    float* out = (float*)d_out;

    static int smem_set = 0;
    if (!smem_set) {
        cudaFuncSetAttribute(k_fattn, cudaFuncAttributeMaxDynamicSharedMemorySize, FA_SMEM);
        smem_set = 1;
    }

    float *px, *pattn;
    uint2 *pxp, *pqkvp, *phidp, *pwqkv, *pwfc1, *pwfc2;
    float *pbqkv;
    cudaGetSymbolAddress((void**)&px, g_x);
    cudaGetSymbolAddress((void**)&pattn, g_attn);
    cudaGetSymbolAddress((void**)&pxp, g_xp);
    cudaGetSymbolAddress((void**)&pqkvp, g_qkvp);
    cudaGetSymbolAddress((void**)&phidp, g_hidp);
    cudaGetSymbolAddress((void**)&pwqkv, g_wqkv);
    cudaGetSymbolAddress((void**)&pwfc1, g_wfc1);
    cudaGetSymbolAddress((void**)&pwfc2, g_wfc2);
    cudaGetSymbolAddress((void**)&pbqkv, g_bqkv);

    const int M = Bb * Ss;  // 4096

    k_pack_qkv<<<((Ee / 2) * 1536 + 255) / 256, 256>>>(q_w, k_w, v_w, q_b, k_b, v_b);
    k_pack_w<<<((Ee / 2) * HIDh + 255) / 256, 256>>>(fc1_w, pwfc1, Ee / 2, HIDh);
    k_pack_w<<<((HIDh / 2) * Ee + 255) / 256, 256>>>(fc2_w, pwfc2, HIDh / 2, Ee);

    k_embed<<<(Bb * Ss * (Ee / 2) + 255) / 256, 256>>>(inputs, emb);

    for (int l = 0; l < Ll; l++) {
        // QKV: 128x128 tiles, packed-only output
        k_gemm128<1, 0, 1><<<dim3(1536 / 128, M / 128), 256>>>(
            pxp, pwqkv, pbqkv, pqkvp, Ee, Ee / 2, 1536, 1536);

        k_build_vs<<<(Bb * Hh * (SKk / 2) * (DHh / 2) + 255) / 256, 256>>>();

        dim3 gf(Ss / 64, Bb * Hh);
        k_fattn<<<gf, 256, FA_SMEM>>>();

        k_ln<<<M, 256>>>(pattn, ln_w, ln_b, px, pxp);

        // fc1: 128x128 tiles, relu, packed-only output
        k_gemm128<1, 1, 1><<<dim3(HIDh / 128, M / 128), 256>>>(
            pxp, pwfc1, fc1_b, phidp, Ee, Ee / 2, HIDh, HIDh);
        // fc2: 64-wide core (residual + fp32 out)
        dim3 g2(Ee / 64, M / 128);
        k_fc2<<<g2, 256>>>(fc2_b);

        k_ln<<<M, 256>>>(pattn, ln_w, ln_b, px, pxp);
    }

    dim3 go(CHUNKS, Bb);
    k_out_partial<<<go, 256>>>(out_w);
    k_out_final<<<Bb, 32>>>(out_b, out);
}